// round 6
// baseline (speedup 1.0000x reference)
#include <cuda_runtime.h>
#include <cuda_bf16.h>
#include <cstdint>
#include <math.h>

#define NB   4
#define NC   256
#define NPIX 4096

// ================= scratch (no allocations allowed) =================
__device__ __align__(128) __nv_bfloat16 g_xs_hi[(size_t)NB*NPIX*NC];
__device__ __align__(128) __nv_bfloat16 g_xs_lo[(size_t)NB*NPIX*NC];
__device__ __align__(128) __nv_bfloat16 g_xo_hi[(size_t)NB*NPIX*NC];
__device__ __align__(128) __nv_bfloat16 g_xo_lo[(size_t)NB*NPIX*NC];
__device__ __align__(128) __nv_bfloat16 g_qt_hi[(size_t)NB*NPIX*NC];   // Q^T [n][c]
__device__ __align__(128) __nv_bfloat16 g_qt_lo[(size_t)NB*NPIX*NC];
__device__ __align__(128) __nv_bfloat16 g_kt_hi[(size_t)NB*NPIX*NC];   // K^T [m][c]
__device__ __align__(128) __nv_bfloat16 g_kt_lo[(size_t)NB*NPIX*NC];
__device__ __align__(128) __nv_bfloat16 g_v_hi [(size_t)NB*NC*NPIX];   // V [c][m]
__device__ __align__(128) __nv_bfloat16 g_v_lo [(size_t)NB*NC*NPIX];
__device__ __align__(128) float         g_attn [(size_t)NB*NPIX*NPIX]; // S fp32
__device__ __align__(128) __nv_bfloat16 g_p_hi [(size_t)NB*NPIX*NPIX]; // P [n][m]
__device__ __align__(128) __nv_bfloat16 g_p_lo [(size_t)NB*NPIX*NPIX];
__device__ __align__(128) float         g_o    [(size_t)NB*NPIX*NC];   // O [n][c]
__device__ __align__(128) float         g_fused[(size_t)NB*NC*NPIX];   // fused [c][n]
__device__ __align__(128) __nv_bfloat16 g_ft_hi[(size_t)NB*NPIX*NC];   // fused^T [n][c]
__device__ __align__(128) __nv_bfloat16 g_ft_lo[(size_t)NB*NPIX*NC];
__device__ __align__(128) __nv_bfloat16 g_qw_hi[NC*NC],   g_qw_lo[NC*NC];
__device__ __align__(128) __nv_bfloat16 g_kvw_hi[2*NC*NC],g_kvw_lo[2*NC*NC];
__device__ __align__(128) __nv_bfloat16 g_ow_hi[NC*NC],   g_ow_lo[NC*NC];
__device__ float g_gate[NB];

// ================= helpers =================
__device__ __forceinline__ uint32_t smem_u32(const void* p) {
    uint32_t a;
    asm("{ .reg .u64 t; cvta.to.shared.u64 t, %1; cvt.u32.u64 %0, t; }" : "=r"(a) : "l"(p));
    return a;
}
__device__ __forceinline__ void ldm_x4(uint32_t* r, uint32_t addr) {
    asm volatile("ldmatrix.sync.aligned.m8n8.x4.shared.b16 {%0,%1,%2,%3}, [%4];"
        : "=r"(r[0]), "=r"(r[1]), "=r"(r[2]), "=r"(r[3]) : "r"(addr));
}
__device__ __forceinline__ void mma16816(float* d, const uint32_t* a, uint32_t b0, uint32_t b1) {
    asm volatile("mma.sync.aligned.m16n8k16.row.col.f32.bf16.bf16.f32 "
        "{%0,%1,%2,%3}, {%4,%5,%6,%7}, {%8,%9}, {%0,%1,%2,%3};"
        : "+f"(d[0]), "+f"(d[1]), "+f"(d[2]), "+f"(d[3])
        : "r"(a[0]), "r"(a[1]), "r"(a[2]), "r"(a[3]), "r"(b0), "r"(b1));
}
#define CP_ASYNC16(saddr, gptr) \
    asm volatile("cp.async.cg.shared.global [%0], [%1], 16;" :: "r"(saddr), "l"(gptr))
#define CP_COMMIT() asm volatile("cp.async.commit_group;" ::: "memory")
#define CP_WAIT0()  asm volatile("cp.async.wait_group 0;" ::: "memory")

// SW128 swizzle on byte offset within a 128B-row tile
__device__ __forceinline__ uint32_t swz(uint32_t o) { return o ^ ((o >> 3) & 0x70); }

// ================= mma.sync GEMM: D[m][n] = alpha*sum_k A[m][k]*B[n][k] + bias =================
// A,B bf16 hi/lo K-major (row stride = K). CTA tile 128x256, warp tile 64x64 (2x4 warps).
// K-chunks of 64, double-buffered cp.async. Requires M%128==0, N%256==0, K%64==0.
// BIAS_MODE: 0 none, 1 per-row (M), 2 per-col (N). OUT_BF16: emit hi/lo bf16.
#define A_TILE  16384             // 128 rows x 128 bytes
#define B_TILE  32768             // 256 rows x 128 bytes
#define STG_B   (2*A_TILE + 2*B_TILE)   // AH AL BH BL = 98304
#define SM_TOT  (2 * STG_B)             // 196608

__device__ __forceinline__ void cp_tileA(uint32_t dst, const __nv_bfloat16* src,
                                         int K, int tid) {
    #pragma unroll
    for (int r = 0; r < 4; r++) {
        int idx = tid + (r << 8);
        int row = idx >> 3, cc = idx & 7;
        CP_ASYNC16(dst + swz(row * 128 + cc * 16), src + (size_t)row * K + cc * 8);
    }
}
__device__ __forceinline__ void cp_tileB(uint32_t dst, const __nv_bfloat16* src,
                                         int K, int tid) {
    #pragma unroll
    for (int r = 0; r < 8; r++) {
        int idx = tid + (r << 8);
        int row = idx >> 3, cc = idx & 7;
        CP_ASYNC16(dst + swz(row * 128 + cc * 16), src + (size_t)row * K + cc * 8);
    }
}

template<int BIAS_MODE, bool OUT_BF16>
__global__ __launch_bounds__(256, 1)
void mma_gemm(const __nv_bfloat16* __restrict__ Ah, const __nv_bfloat16* __restrict__ Al,
              const __nv_bfloat16* __restrict__ Bh, const __nv_bfloat16* __restrict__ Bl,
              const float* __restrict__ bias, float alpha,
              float* __restrict__ Cf, __nv_bfloat16* __restrict__ Ch, __nv_bfloat16* __restrict__ Cl,
              int K, int ldc, long long sA, long long sB, long long sC)
{
    extern __shared__ __align__(1024) char dsm[];
    const uint32_t sb = smem_u32(dsm);
    const int tid = threadIdx.x, wid = tid >> 5, lane = tid & 31;
    const int warp_m = wid >> 2;        // 0..1  (64 rows each)
    const int warp_n = wid & 3;         // 0..3  (64 cols each)

    const size_t m0 = (size_t)blockIdx.y << 7;
    const size_t n0 = (size_t)blockIdx.x << 8;
    const __nv_bfloat16* pah = Ah + (long long)blockIdx.z * sA + m0 * K;
    const __nv_bfloat16* pal = Al + (long long)blockIdx.z * sA + m0 * K;
    const __nv_bfloat16* pbh = Bh + (long long)blockIdx.z * sB + n0 * K;
    const __nv_bfloat16* pbl = Bl + (long long)blockIdx.z * sB + n0 * K;

    float acc[4][8][4];
    #pragma unroll
    for (int i = 0; i < 4; i++)
        #pragma unroll
        for (int j = 0; j < 8; j++)
            #pragma unroll
            for (int q = 0; q < 4; q++) acc[i][j][q] = 0.f;

    const int nch = K >> 6;
    cp_tileA(sb,                       pah, K, tid);
    cp_tileA(sb + A_TILE,              pal, K, tid);
    cp_tileB(sb + 2*A_TILE,            pbh, K, tid);
    cp_tileB(sb + 2*A_TILE + B_TILE,   pbl, K, tid);
    CP_COMMIT();

    for (int ch = 0; ch < nch; ch++) {
        CP_WAIT0();
        __syncthreads();
        if (ch + 1 < nch) {
            const size_t k0 = (size_t)(ch + 1) << 6;
            const uint32_t nb = sb + ((ch + 1) & 1) * STG_B;
            cp_tileA(nb,                      pah + k0, K, tid);
            cp_tileA(nb + A_TILE,             pal + k0, K, tid);
            cp_tileB(nb + 2*A_TILE,           pbh + k0, K, tid);
            cp_tileB(nb + 2*A_TILE + B_TILE,  pbl + k0, K, tid);
            CP_COMMIT();
        }
        const uint32_t cbAH = sb + (ch & 1) * STG_B;
        const uint32_t cbAL = cbAH + A_TILE;
        const uint32_t cbBH = cbAH + 2 * A_TILE;
        const uint32_t cbBL = cbBH + B_TILE;

        #pragma unroll
        for (int ks = 0; ks < 4; ks++) {
            const uint32_t koff = ks * 32 + (lane >> 4) * 16;
            uint32_t a_hi[4][4], a_lo[4][4];
            #pragma unroll
            for (int im = 0; im < 4; im++) {
                uint32_t off = swz((warp_m * 64 + im * 16 + (lane & 15)) * 128 + koff);
                ldm_x4(a_hi[im], cbAH + off);
                ldm_x4(a_lo[im], cbAL + off);
            }
            #pragma unroll
            for (int in2 = 0; in2 < 4; in2++) {
                uint32_t off = swz((warp_n * 64 + in2 * 16 + (lane & 15)) * 128 + koff);
                uint32_t bh[4], bl[4];
                ldm_x4(bh, cbBH + off);
                ldm_x4(bl, cbBL + off);
                #pragma unroll
                for (int im = 0; im < 4; im++) {
                    #pragma unroll
                    for (int s = 0; s < 2; s++) {
                        float* d = acc[im][in2 * 2 + s];
                        mma16816(d, a_hi[im], bh[s], bh[s + 2]);
                        mma16816(d, a_hi[im], bl[s], bl[s + 2]);
                        mma16816(d, a_lo[im], bh[s], bh[s + 2]);
                    }
                }
            }
        }
        __syncthreads();
    }

    // ---------------- epilogue ----------------
    const long long cbase = (long long)blockIdx.z * sC;
    #pragma unroll
    for (int im = 0; im < 4; im++) {
        const int r0 = (int)m0 + warp_m * 64 + im * 16 + (lane >> 2);
        const int r1 = r0 + 8;
        float rb0 = 0.f, rb1 = 0.f;
        if (BIAS_MODE == 1) { rb0 = bias[r0]; rb1 = bias[r1]; }
        #pragma unroll
        for (int in = 0; in < 8; in++) {
            const int c = (int)n0 + warp_n * 64 + in * 8 + (lane & 3) * 2;
            float cb0 = rb0, cb1 = rb0, cb2 = rb1, cb3 = rb1;
            if (BIAS_MODE == 2) { cb0 = cb2 = bias[c]; cb1 = cb3 = bias[c + 1]; }
            float v0 = fmaf(alpha, acc[im][in][0], cb0);
            float v1 = fmaf(alpha, acc[im][in][1], cb1);
            float v2 = fmaf(alpha, acc[im][in][2], cb2);
            float v3 = fmaf(alpha, acc[im][in][3], cb3);
            if (OUT_BF16) {
                __nv_bfloat16 h0 = __float2bfloat16(v0), h1 = __float2bfloat16(v1);
                __nv_bfloat16 h2 = __float2bfloat16(v2), h3 = __float2bfloat16(v3);
                *reinterpret_cast<__nv_bfloat162*>(Ch + cbase + (size_t)r0 * ldc + c) =
                    __nv_bfloat162(h0, h1);
                *reinterpret_cast<__nv_bfloat162*>(Ch + cbase + (size_t)r1 * ldc + c) =
                    __nv_bfloat162(h2, h3);
                *reinterpret_cast<__nv_bfloat162*>(Cl + cbase + (size_t)r0 * ldc + c) =
                    __nv_bfloat162(__float2bfloat16(v0 - __bfloat162float(h0)),
                                   __float2bfloat16(v1 - __bfloat162float(h1)));
                *reinterpret_cast<__nv_bfloat162*>(Cl + cbase + (size_t)r1 * ldc + c) =
                    __nv_bfloat162(__float2bfloat16(v2 - __bfloat162float(h2)),
                                   __float2bfloat16(v3 - __bfloat162float(h3)));
            } else {
                *reinterpret_cast<float2*>(Cf + cbase + (size_t)r0 * ldc + c) = make_float2(v0, v1);
                *reinterpret_cast<float2*>(Cf + cbase + (size_t)r1 * ldc + c) = make_float2(v2, v3);
            }
        }
    }
}

// ================= transpose + split: src fp32 [R][C] -> dst hi/lo bf16 [C][R] =================
__global__ void tconv(const float* __restrict__ src, __nv_bfloat16* __restrict__ dh,
                      __nv_bfloat16* __restrict__ dl, int R, int C)
{
    src += (size_t)blockIdx.z * R * C;
    dh  += (size_t)blockIdx.z * R * C;
    dl  += (size_t)blockIdx.z * R * C;
    __shared__ float t[32][33];
    const int c0 = blockIdx.x * 32, r0 = blockIdx.y * 32;
    const int tx = threadIdx.x, ty = threadIdx.y;
    #pragma unroll
    for (int i = 0; i < 4; i++)
        t[ty + 8 * i][tx] = src[(size_t)(r0 + ty + 8 * i) * C + c0 + tx];
    __syncthreads();
    #pragma unroll
    for (int i = 0; i < 4; i++) {
        float v = t[tx][ty + 8 * i];
        size_t o = (size_t)(c0 + ty + 8 * i) * R + r0 + tx;
        __nv_bfloat16 h = __float2bfloat16(v);
        dh[o] = h;
        dl[o] = __float2bfloat16(v - __bfloat162float(h));
    }
}

// ================= flat split (weights) =================
__global__ void fsplit(const float* __restrict__ src, __nv_bfloat16* __restrict__ dh,
                       __nv_bfloat16* __restrict__ dl, int n)
{
    int i = blockIdx.x * 256 + threadIdx.x;
    if (i < n) {
        float v = src[i];
        __nv_bfloat16 h = __float2bfloat16(v);
        dh[i] = h;
        dl[i] = __float2bfloat16(v - __bfloat162float(h));
    }
}

// ================= softmax: fp32 S row -> P hi/lo bf16 =================
__global__ __launch_bounds__(256)
void softmax_rows()
{
    const size_t ro = (size_t)blockIdx.x * NPIX;
    const float4* row = (const float4*)(g_attn + ro);
    const int tid = threadIdx.x;
    float4 v[4];
    #pragma unroll
    for (int i = 0; i < 4; i++) v[i] = row[tid + (i << 8)];

    float m = v[0].x;
    #pragma unroll
    for (int i = 0; i < 4; i++)
        m = fmaxf(m, fmaxf(fmaxf(v[i].x, v[i].y), fmaxf(v[i].z, v[i].w)));
    #pragma unroll
    for (int o = 16; o; o >>= 1) m = fmaxf(m, __shfl_xor_sync(0xffffffffu, m, o));
    __shared__ float sm[8], ss[8];
    if ((tid & 31) == 0) sm[tid >> 5] = m;
    __syncthreads();
    #pragma unroll
    for (int w = 0; w < 8; w++) m = fmaxf(m, sm[w]);

    float s = 0.f;
    #pragma unroll
    for (int i = 0; i < 4; i++) {
        v[i].x = __expf(v[i].x - m); s += v[i].x;
        v[i].y = __expf(v[i].y - m); s += v[i].y;
        v[i].z = __expf(v[i].z - m); s += v[i].z;
        v[i].w = __expf(v[i].w - m); s += v[i].w;
    }
    #pragma unroll
    for (int o = 16; o; o >>= 1) s += __shfl_xor_sync(0xffffffffu, s, o);
    if ((tid & 31) == 0) ss[tid >> 5] = s;
    __syncthreads();
    s = 0.f;
    #pragma unroll
    for (int w = 0; w < 8; w++) s += ss[w];

    const float r = 1.f / s;
    __nv_bfloat16* ph = g_p_hi + ro;
    __nv_bfloat16* pl = g_p_lo + ro;
    #pragma unroll
    for (int i = 0; i < 4; i++) {
        float p0 = v[i].x * r, p1 = v[i].y * r, p2 = v[i].z * r, p3 = v[i].w * r;
        __nv_bfloat16 h0 = __float2bfloat16(p0), h1 = __float2bfloat16(p1);
        __nv_bfloat16 h2 = __float2bfloat16(p2), h3 = __float2bfloat16(p3);
        int c0 = 4 * tid + 1024 * i;
        *reinterpret_cast<__nv_bfloat162*>(ph + c0)     = __nv_bfloat162(h0, h1);
        *reinterpret_cast<__nv_bfloat162*>(ph + c0 + 2) = __nv_bfloat162(h2, h3);
        *reinterpret_cast<__nv_bfloat162*>(pl + c0) =
            __nv_bfloat162(__float2bfloat16(p0 - __bfloat162float(h0)),
                           __float2bfloat16(p1 - __bfloat162float(h1)));
        *reinterpret_cast<__nv_bfloat162*>(pl + c0 + 2) =
            __nv_bfloat162(__float2bfloat16(p2 - __bfloat162float(h2)),
                           __float2bfloat16(p3 - __bfloat162float(h3)));
    }
}

// ================= gate MLP =================
__global__ __launch_bounds__(256)
void gate_kernel(const float* __restrict__ xs,
                 const float* __restrict__ g1w, const float* __restrict__ g1b,
                 const float* __restrict__ g2w, const float* __restrict__ g2b)
{
    const int b = blockIdx.x, tid = threadIdx.x;
    const int wid = tid >> 5, lane = tid & 31;
    __shared__ float p[NC];
    const float* x = xs + (size_t)b * NC * NPIX;
    for (int c = wid; c < NC; c += 8) {
        const float* xc = x + (size_t)c * NPIX;
        float s = 0.f;
        for (int i = lane; i < NPIX; i += 32) s += xc[i];
        #pragma unroll
        for (int o = 16; o; o >>= 1) s += __shfl_xor_sync(0xffffffffu, s, o);
        if (!lane) p[c] = s * (1.0f / NPIX);
    }
    __syncthreads();
    __shared__ float hbuf[64];
    if (tid < 64) {
        float s = g1b[tid];
        for (int c = 0; c < NC; c++) s = fmaf(g1w[tid * NC + c], p[c], s);
        hbuf[tid] = fmaxf(s, 0.f);
    }
    __syncthreads();
    if (tid == 0) {
        float s = g2b[0];
        #pragma unroll
        for (int o = 0; o < 64; o++) s = fmaf(g2w[o], hbuf[o], s);
        g_gate[b] = 1.f / (1.f + __expf(-s));
    }
}

// ================= dwconv3x3 + BN + SiLU + gate*O -> fused [c][n] =================
__global__ __launch_bounds__(256)
void fuse_kernel(const float* __restrict__ xs,
                 const float* __restrict__ dww, const float* __restrict__ dwb,
                 const float* __restrict__ bng, const float* __restrict__ bnb,
                 const float* __restrict__ bnm, const float* __restrict__ bnv)
{
    const int bc = blockIdx.x;
    const int b = bc >> 8, c = bc & 255;
    const int tid = threadIdx.x;
    __shared__ float t[66 * 66];
    const float* x = xs + (size_t)bc * NPIX;
    for (int i = tid; i < 66 * 66; i += 256) {
        int h = i / 66 - 1, w = i % 66 - 1;
        t[i] = (h >= 0 && h < 64 && w >= 0 && w < 64) ? x[h * 64 + w] : 0.f;
    }
    float wt[9];
    #pragma unroll
    for (int k = 0; k < 9; k++) wt[k] = dww[c * 9 + k];
    float scale = bng[c] * rsqrtf(bnv[c] + 1e-5f);
    float shift = fmaf(dwb[c] - bnm[c], scale, bnb[c]);
    float gate = g_gate[b];
    float* fptr = g_fused + (size_t)bc * NPIX;
    const float* optr = g_o + (size_t)b * NPIX * NC;   // [n][c]
    __syncthreads();
    for (int i = tid; i < NPIX; i += 256) {
        int h = i >> 6, w = i & 63;
        const float* tp = &t[h * 66 + w];
        float conv = tp[0]   * wt[0] + tp[1]   * wt[1] + tp[2]   * wt[2]
                   + tp[66]  * wt[3] + tp[67]  * wt[4] + tp[68]  * wt[5]
                   + tp[132] * wt[6] + tp[133] * wt[7] + tp[134] * wt[8];
        float y = fmaf(conv, scale, shift);
        float lf = y / (1.f + __expf(-y));
        fptr[i] = fmaf(gate, optr[(size_t)i * NC + c], lf);
    }
}

// ================= launch =================
extern "C" void kernel_launch(void* const* d_in, const int* in_sizes, int n_in,
                              void* d_out, int out_size)
{
    const float* x_self  = (const float*)d_in[0];
    const float* x_other = (const float*)d_in[1];
    const float* q_w  = (const float*)d_in[2];
    const float* q_b  = (const float*)d_in[3];
    const float* kv_w = (const float*)d_in[4];
    const float* kv_b = (const float*)d_in[5];
    const float* g1_w = (const float*)d_in[6];
    const float* g1_b = (const float*)d_in[7];
    const float* g2_w = (const float*)d_in[8];
    const float* g2_b = (const float*)d_in[9];
    const float* dw_w = (const float*)d_in[10];
    const float* dw_b = (const float*)d_in[11];
    const float* bn_g = (const float*)d_in[12];
    const float* bn_b = (const float*)d_in[13];
    const float* bn_m = (const float*)d_in[14];
    const float* bn_v = (const float*)d_in[15];
    const float* out_w = (const float*)d_in[16];
    const float* out_b = (const float*)d_in[17];
    float* out = (float*)d_out;

    cudaFuncSetAttribute(mma_gemm<2, true>,  cudaFuncAttributeMaxDynamicSharedMemorySize, SM_TOT);
    cudaFuncSetAttribute(mma_gemm<1, true>,  cudaFuncAttributeMaxDynamicSharedMemorySize, SM_TOT);
    cudaFuncSetAttribute(mma_gemm<0, false>, cudaFuncAttributeMaxDynamicSharedMemorySize, SM_TOT);
    cudaFuncSetAttribute(mma_gemm<1, false>, cudaFuncAttributeMaxDynamicSharedMemorySize, SM_TOT);

    #define SYM(p, s) cudaGetSymbolAddress((void**)&p, s)
    __nv_bfloat16 *xsh, *xsl, *xoh, *xol, *qth, *qtl, *kth, *ktl, *vh, *vl;
    __nv_bfloat16 *ph, *pl, *fth, *ftl, *qwh, *qwl, *kvwh, *kvwl, *owh, *owl;
    float *sp, *op, *fp;
    SYM(xsh, g_xs_hi); SYM(xsl, g_xs_lo); SYM(xoh, g_xo_hi); SYM(xol, g_xo_lo);
    SYM(qth, g_qt_hi); SYM(qtl, g_qt_lo); SYM(kth, g_kt_hi); SYM(ktl, g_kt_lo);
    SYM(vh, g_v_hi);   SYM(vl, g_v_lo);   SYM(ph, g_p_hi);   SYM(pl, g_p_lo);
    SYM(fth, g_ft_hi); SYM(ftl, g_ft_lo); SYM(qwh, g_qw_hi); SYM(qwl, g_qw_lo);
    SYM(kvwh, g_kvw_hi); SYM(kvwl, g_kvw_lo); SYM(owh, g_ow_hi); SYM(owl, g_ow_lo);
    SYM(sp, g_attn);   SYM(op, g_o);      SYM(fp, g_fused);
    #undef SYM

    const long long sX = (long long)NPIX * NC;
    const long long sS = (long long)NPIX * NPIX;

    // weight splits + input transpose-splits
    fsplit<<<(NC * NC + 255) / 256, 256>>>(q_w, qwh, qwl, NC * NC);
    fsplit<<<(2 * NC * NC + 255) / 256, 256>>>(kv_w, kvwh, kvwl, 2 * NC * NC);
    fsplit<<<(NC * NC + 255) / 256, 256>>>(out_w, owh, owl, NC * NC);
    tconv<<<dim3(NPIX / 32, NC / 32, NB), dim3(32, 8)>>>(x_self,  xsh, xsl, NC, NPIX);
    tconv<<<dim3(NPIX / 32, NC / 32, NB), dim3(32, 8)>>>(x_other, xoh, xol, NC, NPIX);

    gate_kernel<<<NB, 256>>>(x_self, g1_w, g1_b, g2_w, g2_b);

    // Qt[n][o] = sum_c xs[n][c] qw[o][c] + q_b[o]   (bf16 out, col bias)  M=4096 N=256
    mma_gemm<2, true><<<dim3(1, 32, NB), 256, SM_TOT>>>(
        xsh, xsl, qwh, qwl, q_b, 1.f, nullptr, qth, qtl, NC, NC, sX, 0, sX);
    // Kt[m][o] = sum_c xo[m][c] kvw[o][c] + kv_b[o]   M=4096 N=256
    mma_gemm<2, true><<<dim3(1, 32, NB), 256, SM_TOT>>>(
        xoh, xol, kvwh, kvwl, kv_b, 1.f, nullptr, kth, ktl, NC, NC, sX, 0, sX);
    // V[c][n] = sum_k kvw[256+c][k] xo[n][k] + kv_b[256+c]   M=256 N=4096 (row bias)
    mma_gemm<1, true><<<dim3(16, 2, NB), 256, SM_TOT>>>(
        kvwh + NC * NC, kvwl + NC * NC, xoh, xol, kv_b + NC, 1.f,
        nullptr, vh, vl, NC, NPIX, 0, sX, sX);
    // S[n][m] = (1/16) sum_c Qt[n][c] Kt[m][c]   M=N=4096 (fp32 out)
    mma_gemm<0, false><<<dim3(16, 32, NB), 256, SM_TOT>>>(
        qth, qtl, kth, ktl, nullptr, 0.0625f, sp, nullptr, nullptr, NC, NPIX, sX, sX, sS);

    softmax_rows<<<NB * NPIX, 256>>>();

    // O[n][c] = sum_m P[n][m] V[c][m]   M=4096 N=256 (fp32 out, ldc=256)
    mma_gemm<0, false><<<dim3(1, 32, NB), 256, SM_TOT>>>(
        ph, pl, vh, vl, nullptr, 1.f, op, nullptr, nullptr, NPIX, NC, sS, sX, sX);

    fuse_kernel<<<NB * NC, 256>>>(x_self, dw_w, dw_b, bn_g, bn_b, bn_m, bn_v);
    tconv<<<dim3(NPIX / 32, NC / 32, NB), dim3(32, 8)>>>(fp, fth, ftl, NC, NPIX);

    // out[o][n] = sum_c ow[o][c] ft[n][c] + out_b[o]   M=256 N=4096 (fp32, row bias)
    mma_gemm<1, false><<<dim3(16, 2, NB), 256, SM_TOT>>>(
        owh, owl, fth, ftl, out_b, 1.f, out, nullptr, nullptr, NC, NPIX, 0, sX, sX);
}

// round 7
// speedup vs baseline: 1.2701x; 1.2701x over previous
#include <cuda_runtime.h>
#include <cuda_fp16.h>
#include <cstdint>
#include <math.h>

#define NB   4
#define NC   256
#define NPIX 4096

// ================= scratch (no allocations allowed) =================
__device__ __align__(128) __half g_xs_hi[(size_t)NB*NPIX*NC];
__device__ __align__(128) __half g_xs_lo[(size_t)NB*NPIX*NC];
__device__ __align__(128) __half g_xo_hi[(size_t)NB*NPIX*NC];
__device__ __align__(128) __half g_xo_lo[(size_t)NB*NPIX*NC];
__device__ __align__(128) __half g_qt_hi[(size_t)NB*NPIX*NC];   // Q^T [n][c]
__device__ __align__(128) __half g_qt_lo[(size_t)NB*NPIX*NC];
__device__ __align__(128) __half g_kt_hi[(size_t)NB*NPIX*NC];   // K^T [m][c]
__device__ __align__(128) __half g_kt_lo[(size_t)NB*NPIX*NC];
__device__ __align__(128) __half g_v_hi [(size_t)NB*NC*NPIX];   // V [c][m]
__device__ __align__(128) __half g_v_lo [(size_t)NB*NC*NPIX];
__device__ __align__(128) float  g_attn [(size_t)NB*NPIX*NPIX]; // S fp32
__device__ __align__(128) __half g_p_hi [(size_t)NB*NPIX*NPIX]; // P [n][m]
__device__ __align__(128) __half g_p_lo [(size_t)NB*NPIX*NPIX];
__device__ __align__(128) float  g_o    [(size_t)NB*NPIX*NC];   // O [n][c]
__device__ __align__(128) float  g_fused[(size_t)NB*NC*NPIX];   // fused [c][n]
__device__ __align__(128) __half g_ft_hi[(size_t)NB*NPIX*NC];   // fused^T [n][c]
__device__ __align__(128) __half g_ft_lo[(size_t)NB*NPIX*NC];
__device__ __align__(128) __half g_qw_hi[NC*NC],   g_qw_lo[NC*NC];
__device__ __align__(128) __half g_kvw_hi[2*NC*NC],g_kvw_lo[2*NC*NC];
__device__ __align__(128) __half g_ow_hi[NC*NC],   g_ow_lo[NC*NC];
__device__ float g_gate[NB];

// ================= helpers =================
__device__ __forceinline__ uint32_t smem_u32(const void* p) {
    uint32_t a;
    asm("{ .reg .u64 t; cvta.to.shared.u64 t, %1; cvt.u32.u64 %0, t; }" : "=r"(a) : "l"(p));
    return a;
}
__device__ __forceinline__ void ldm_x4(uint32_t* r, uint32_t addr) {
    asm volatile("ldmatrix.sync.aligned.m8n8.x4.shared.b16 {%0,%1,%2,%3}, [%4];"
        : "=r"(r[0]), "=r"(r[1]), "=r"(r[2]), "=r"(r[3]) : "r"(addr));
}
__device__ __forceinline__ void mma_f16(float* d, const uint32_t* a, uint32_t b0, uint32_t b1) {
    asm volatile("mma.sync.aligned.m16n8k16.row.col.f32.f16.f16.f32 "
        "{%0,%1,%2,%3}, {%4,%5,%6,%7}, {%8,%9}, {%0,%1,%2,%3};"
        : "+f"(d[0]), "+f"(d[1]), "+f"(d[2]), "+f"(d[3])
        : "r"(a[0]), "r"(a[1]), "r"(a[2]), "r"(a[3]), "r"(b0), "r"(b1));
}
#define CP_ASYNC16(saddr, gptr) \
    asm volatile("cp.async.cg.shared.global [%0], [%1], 16;" :: "r"(saddr), "l"(gptr))
#define CP_COMMIT() asm volatile("cp.async.commit_group;" ::: "memory")
#define CP_WAIT0()  asm volatile("cp.async.wait_group 0;" ::: "memory")

// SW128 swizzle on byte offset within a 128B-row tile
__device__ __forceinline__ uint32_t swz(uint32_t o) { return o ^ ((o >> 3) & 0x70); }

__device__ __forceinline__ void split2(float v, __half& h, __half& l) {
    h = __float2half(v);
    l = __float2half(v - __half2float(h));
}

// ================= mma.sync GEMM: D[m][n] = alpha*sum_k A[m][k]*B[n][k] + bias =================
// A,B fp16 K-major (row stride = K). A has hi/lo split; B lo used only when NTERMS==3.
// NTERMS=2: C = Ah*Bh + Al*Bh (B quantization error ~2^-12)
// NTERMS=3: C = Ah*Bh + Al*Bh + Ah*Bl (error ~2^-24)
// CTA tile 128x128, warp tile 32x64 (4x2 warps), K-chunks of 64, double-buffered cp.async.
// BIAS_MODE: 0 none, 1 per-row (M), 2 per-col (N). OUT_F16: emit hi/lo fp16.
#define A_TILE  16384                         // 128 rows x 128 bytes
#define SMTOT2  (2 * 3 * A_TILE)              // 98304  (AH AL BH)  -> 2 CTAs/SM
#define SMTOT3  (2 * 4 * A_TILE)              // 131072 (AH AL BH BL)

__device__ __forceinline__ void cp_tile(uint32_t dst, const __half* src, int K, int tid) {
    #pragma unroll
    for (int r = 0; r < 4; r++) {
        int idx = tid + (r << 8);
        int row = idx >> 3, cc = idx & 7;
        CP_ASYNC16(dst + swz(row * 128 + cc * 16), src + (size_t)row * K + cc * 8);
    }
}

template<int NTERMS, int BIAS_MODE, bool OUT_F16>
__global__ __launch_bounds__(256, NTERMS == 2 ? 2 : 1)
void mma_gemm(const __half* __restrict__ Ah, const __half* __restrict__ Al,
              const __half* __restrict__ Bh, const __half* __restrict__ Bl,
              const float* __restrict__ bias, float alpha,
              float* __restrict__ Cf, __half* __restrict__ Ch, __half* __restrict__ Cl,
              int K, int ldc, long long sA, long long sB, long long sC)
{
    constexpr uint32_t STG = (NTERMS == 2 ? 3 : 4) * A_TILE;
    extern __shared__ __align__(1024) char dsm[];
    const uint32_t sb = smem_u32(dsm);
    const int tid = threadIdx.x, wid = tid >> 5, lane = tid & 31;
    const int warp_m = wid & 3, warp_n = wid >> 2;     // 4 x 2 warps, warp tile 32x64

    const size_t m0 = (size_t)blockIdx.y << 7;
    const size_t n0 = (size_t)blockIdx.x << 7;
    const __half* pah = Ah + (long long)blockIdx.z * sA + m0 * K;
    const __half* pal = Al + (long long)blockIdx.z * sA + m0 * K;
    const __half* pbh = Bh + (long long)blockIdx.z * sB + n0 * K;
    const __half* pbl = (NTERMS == 3) ? (Bl + (long long)blockIdx.z * sB + n0 * K) : nullptr;

    float acc[2][8][4];
    #pragma unroll
    for (int i = 0; i < 2; i++)
        #pragma unroll
        for (int j = 0; j < 8; j++)
            #pragma unroll
            for (int q = 0; q < 4; q++) acc[i][j][q] = 0.f;

    const int nch = K >> 6;
    cp_tile(sb,              pah, K, tid);
    cp_tile(sb +   A_TILE,   pal, K, tid);
    cp_tile(sb + 2*A_TILE,   pbh, K, tid);
    if (NTERMS == 3) cp_tile(sb + 3*A_TILE, pbl, K, tid);
    CP_COMMIT();

    for (int ch = 0; ch < nch; ch++) {
        CP_WAIT0();
        __syncthreads();
        if (ch + 1 < nch) {
            const size_t k0 = (size_t)(ch + 1) << 6;
            const uint32_t nb = sb + ((ch + 1) & 1) * STG;
            cp_tile(nb,              pah + k0, K, tid);
            cp_tile(nb +   A_TILE,   pal + k0, K, tid);
            cp_tile(nb + 2*A_TILE,   pbh + k0, K, tid);
            if (NTERMS == 3) cp_tile(nb + 3*A_TILE, pbl + k0, K, tid);
            CP_COMMIT();
        }
        const uint32_t cbAH = sb + (ch & 1) * STG;
        const uint32_t cbAL = cbAH + A_TILE;
        const uint32_t cbBH = cbAH + 2 * A_TILE;
        const uint32_t cbBL = cbAH + 3 * A_TILE;

        #pragma unroll
        for (int ks = 0; ks < 4; ks++) {
            const uint32_t koff = ks * 32 + (lane >> 4) * 16;
            uint32_t a_hi[2][4], a_lo[2][4];
            #pragma unroll
            for (int im = 0; im < 2; im++) {
                uint32_t off = swz((warp_m * 32 + im * 16 + (lane & 15)) * 128 + koff);
                ldm_x4(a_hi[im], cbAH + off);
                ldm_x4(a_lo[im], cbAL + off);
            }
            #pragma unroll
            for (int in2 = 0; in2 < 4; in2++) {
                uint32_t off = swz((warp_n * 64 + in2 * 16 + (lane & 15)) * 128 + koff);
                uint32_t bh[4];
                ldm_x4(bh, cbBH + off);
                uint32_t bl[4];
                if (NTERMS == 3) ldm_x4(bl, cbBL + off);
                #pragma unroll
                for (int im = 0; im < 2; im++) {
                    #pragma unroll
                    for (int s = 0; s < 2; s++) {
                        float* d = acc[im][in2 * 2 + s];
                        mma_f16(d, a_hi[im], bh[s], bh[s + 2]);
                        mma_f16(d, a_lo[im], bh[s], bh[s + 2]);
                        if (NTERMS == 3) mma_f16(d, a_hi[im], bl[s], bl[s + 2]);
                    }
                }
            }
        }
        __syncthreads();
    }

    // ---------------- epilogue ----------------
    const long long cbase = (long long)blockIdx.z * sC;
    #pragma unroll
    for (int im = 0; im < 2; im++) {
        const int r0 = (int)m0 + warp_m * 32 + im * 16 + (lane >> 2);
        const int r1 = r0 + 8;
        float rb0 = 0.f, rb1 = 0.f;
        if (BIAS_MODE == 1) { rb0 = bias[r0]; rb1 = bias[r1]; }
        #pragma unroll
        for (int in = 0; in < 8; in++) {
            const int c = (int)n0 + warp_n * 64 + in * 8 + (lane & 3) * 2;
            float cb0 = rb0, cb1 = rb0, cb2 = rb1, cb3 = rb1;
            if (BIAS_MODE == 2) { cb0 = cb2 = bias[c]; cb1 = cb3 = bias[c + 1]; }
            float v0 = fmaf(alpha, acc[im][in][0], cb0);
            float v1 = fmaf(alpha, acc[im][in][1], cb1);
            float v2 = fmaf(alpha, acc[im][in][2], cb2);
            float v3 = fmaf(alpha, acc[im][in][3], cb3);
            if (OUT_F16) {
                __half h0, h1, h2, h3, l0, l1, l2, l3;
                split2(v0, h0, l0); split2(v1, h1, l1);
                split2(v2, h2, l2); split2(v3, h3, l3);
                *reinterpret_cast<__half2*>(Ch + cbase + (size_t)r0 * ldc + c) = __halves2half2(h0, h1);
                *reinterpret_cast<__half2*>(Ch + cbase + (size_t)r1 * ldc + c) = __halves2half2(h2, h3);
                *reinterpret_cast<__half2*>(Cl + cbase + (size_t)r0 * ldc + c) = __halves2half2(l0, l1);
                *reinterpret_cast<__half2*>(Cl + cbase + (size_t)r1 * ldc + c) = __halves2half2(l2, l3);
            } else {
                *reinterpret_cast<float2*>(Cf + cbase + (size_t)r0 * ldc + c) = make_float2(v0, v1);
                *reinterpret_cast<float2*>(Cf + cbase + (size_t)r1 * ldc + c) = make_float2(v2, v3);
            }
        }
    }
}

// ================= transpose + split: src fp32 [R][C] -> dst hi/lo fp16 [C][R] =================
__global__ void tconv(const float* __restrict__ src, __half* __restrict__ dh,
                      __half* __restrict__ dl, int R, int C)
{
    src += (size_t)blockIdx.z * R * C;
    dh  += (size_t)blockIdx.z * R * C;
    dl  += (size_t)blockIdx.z * R * C;
    __shared__ float t[32][33];
    const int c0 = blockIdx.x * 32, r0 = blockIdx.y * 32;
    const int tx = threadIdx.x, ty = threadIdx.y;
    #pragma unroll
    for (int i = 0; i < 4; i++)
        t[ty + 8 * i][tx] = src[(size_t)(r0 + ty + 8 * i) * C + c0 + tx];
    __syncthreads();
    #pragma unroll
    for (int i = 0; i < 4; i++) {
        float v = t[tx][ty + 8 * i];
        size_t o = (size_t)(c0 + ty + 8 * i) * R + r0 + tx;
        __half h, l; split2(v, h, l);
        dh[o] = h; dl[o] = l;
    }
}

// ================= combined weight split =================
__global__ void wsplit(const float* __restrict__ qw, const float* __restrict__ kvw,
                       const float* __restrict__ ow)
{
    int i = blockIdx.x * 256 + threadIdx.x;   // 0 .. 262143
    const float* src; __half *dh, *dl; int off;
    if (i < NC * NC)            { src = qw;  dh = g_qw_hi;  dl = g_qw_lo;  off = i; }
    else if (i < 3 * NC * NC)   { src = kvw; dh = g_kvw_hi; dl = g_kvw_lo; off = i - NC * NC; }
    else                        { src = ow;  dh = g_ow_hi;  dl = g_ow_lo;  off = i - 3 * NC * NC; }
    __half h, l; split2(src[off], h, l);
    dh[off] = h; dl[off] = l;
}

// ================= softmax: fp32 S row -> P hi/lo fp16 =================
__global__ __launch_bounds__(256)
void softmax_rows()
{
    const size_t ro = (size_t)blockIdx.x * NPIX;
    const float4* row = (const float4*)(g_attn + ro);
    const int tid = threadIdx.x;
    float4 v[4];
    #pragma unroll
    for (int i = 0; i < 4; i++) v[i] = row[tid + (i << 8)];

    float m = v[0].x;
    #pragma unroll
    for (int i = 0; i < 4; i++)
        m = fmaxf(m, fmaxf(fmaxf(v[i].x, v[i].y), fmaxf(v[i].z, v[i].w)));
    #pragma unroll
    for (int o = 16; o; o >>= 1) m = fmaxf(m, __shfl_xor_sync(0xffffffffu, m, o));
    __shared__ float sm[8], ss[8];
    if ((tid & 31) == 0) sm[tid >> 5] = m;
    __syncthreads();
    #pragma unroll
    for (int w = 0; w < 8; w++) m = fmaxf(m, sm[w]);

    float s = 0.f;
    #pragma unroll
    for (int i = 0; i < 4; i++) {
        v[i].x = __expf(v[i].x - m); s += v[i].x;
        v[i].y = __expf(v[i].y - m); s += v[i].y;
        v[i].z = __expf(v[i].z - m); s += v[i].z;
        v[i].w = __expf(v[i].w - m); s += v[i].w;
    }
    #pragma unroll
    for (int o = 16; o; o >>= 1) s += __shfl_xor_sync(0xffffffffu, s, o);
    if ((tid & 31) == 0) ss[tid >> 5] = s;
    __syncthreads();
    s = 0.f;
    #pragma unroll
    for (int w = 0; w < 8; w++) s += ss[w];

    const float r = 1.f / s;
    __half* ph = g_p_hi + ro;
    __half* pl = g_p_lo + ro;
    #pragma unroll
    for (int i = 0; i < 4; i++) {
        float p0 = v[i].x * r, p1 = v[i].y * r, p2 = v[i].z * r, p3 = v[i].w * r;
        __half h0, h1, h2, h3, l0, l1, l2, l3;
        split2(p0, h0, l0); split2(p1, h1, l1);
        split2(p2, h2, l2); split2(p3, h3, l3);
        int c0 = 4 * tid + 1024 * i;
        *reinterpret_cast<__half2*>(ph + c0)     = __halves2half2(h0, h1);
        *reinterpret_cast<__half2*>(ph + c0 + 2) = __halves2half2(h2, h3);
        *reinterpret_cast<__half2*>(pl + c0)     = __halves2half2(l0, l1);
        *reinterpret_cast<__half2*>(pl + c0 + 2) = __halves2half2(l2, l3);
    }
}

// ================= gate MLP =================
__global__ __launch_bounds__(256)
void gate_kernel(const float* __restrict__ xs,
                 const float* __restrict__ g1w, const float* __restrict__ g1b,
                 const float* __restrict__ g2w, const float* __restrict__ g2b)
{
    const int b = blockIdx.x, tid = threadIdx.x;
    const int wid = tid >> 5, lane = tid & 31;
    __shared__ float p[NC];
    const float* x = xs + (size_t)b * NC * NPIX;
    for (int c = wid; c < NC; c += 8) {
        const float* xc = x + (size_t)c * NPIX;
        float s = 0.f;
        for (int i = lane; i < NPIX; i += 32) s += xc[i];
        #pragma unroll
        for (int o = 16; o; o >>= 1) s += __shfl_xor_sync(0xffffffffu, s, o);
        if (!lane) p[c] = s * (1.0f / NPIX);
    }
    __syncthreads();
    __shared__ float hbuf[64];
    if (tid < 64) {
        float s = g1b[tid];
        for (int c = 0; c < NC; c++) s = fmaf(g1w[tid * NC + c], p[c], s);
        hbuf[tid] = fmaxf(s, 0.f);
    }
    __syncthreads();
    if (tid == 0) {
        float s = g2b[0];
        #pragma unroll
        for (int o = 0; o < 64; o++) s = fmaf(g2w[o], hbuf[o], s);
        g_gate[b] = 1.f / (1.f + __expf(-s));
    }
}

// ================= dwconv3x3 + BN + SiLU + gate*O -> fused [c][n] =================
__global__ __launch_bounds__(256)
void fuse_kernel(const float* __restrict__ xs,
                 const float* __restrict__ dww, const float* __restrict__ dwb,
                 const float* __restrict__ bng, const float* __restrict__ bnb,
                 const float* __restrict__ bnm, const float* __restrict__ bnv)
{
    const int bc = blockIdx.x;
    const int b = bc >> 8, c = bc & 255;
    const int tid = threadIdx.x;
    __shared__ float t[66 * 66];
    const float* x = xs + (size_t)bc * NPIX;
    for (int i = tid; i < 66 * 66; i += 256) {
        int h = i / 66 - 1, w = i % 66 - 1;
        t[i] = (h >= 0 && h < 64 && w >= 0 && w < 64) ? x[h * 64 + w] : 0.f;
    }
    float wt[9];
    #pragma unroll
    for (int k = 0; k < 9; k++) wt[k] = dww[c * 9 + k];
    float scale = bng[c] * rsqrtf(bnv[c] + 1e-5f);
    float shift = fmaf(dwb[c] - bnm[c], scale, bnb[c]);
    float gate = g_gate[b];
    float* fptr = g_fused + (size_t)bc * NPIX;
    const float* optr = g_o + (size_t)b * NPIX * NC;   // [n][c]
    __syncthreads();
    for (int i = tid; i < NPIX; i += 256) {
        int h = i >> 6, w = i & 63;
        const float* tp = &t[h * 66 + w];
        float conv = tp[0]   * wt[0] + tp[1]   * wt[1] + tp[2]   * wt[2]
                   + tp[66]  * wt[3] + tp[67]  * wt[4] + tp[68]  * wt[5]
                   + tp[132] * wt[6] + tp[133] * wt[7] + tp[134] * wt[8];
        float y = fmaf(conv, scale, shift);
        float lf = y / (1.f + __expf(-y));
        fptr[i] = fmaf(gate, optr[(size_t)i * NC + c], lf);
    }
}

// ================= launch =================
extern "C" void kernel_launch(void* const* d_in, const int* in_sizes, int n_in,
                              void* d_out, int out_size)
{
    const float* x_self  = (const float*)d_in[0];
    const float* x_other = (const float*)d_in[1];
    const float* q_w  = (const float*)d_in[2];
    const float* q_b  = (const float*)d_in[3];
    const float* kv_w = (const float*)d_in[4];
    const float* kv_b = (const float*)d_in[5];
    const float* g1_w = (const float*)d_in[6];
    const float* g1_b = (const float*)d_in[7];
    const float* g2_w = (const float*)d_in[8];
    const float* g2_b = (const float*)d_in[9];
    const float* dw_w = (const float*)d_in[10];
    const float* dw_b = (const float*)d_in[11];
    const float* bn_g = (const float*)d_in[12];
    const float* bn_b = (const float*)d_in[13];
    const float* bn_m = (const float*)d_in[14];
    const float* bn_v = (const float*)d_in[15];
    const float* out_w = (const float*)d_in[16];
    const float* out_b = (const float*)d_in[17];
    float* out = (float*)d_out;

    cudaFuncSetAttribute(mma_gemm<3, 2, true>,  cudaFuncAttributeMaxDynamicSharedMemorySize, SMTOT3);
    cudaFuncSetAttribute(mma_gemm<3, 1, true>,  cudaFuncAttributeMaxDynamicSharedMemorySize, SMTOT3);
    cudaFuncSetAttribute(mma_gemm<2, 0, false>, cudaFuncAttributeMaxDynamicSharedMemorySize, SMTOT2);
    cudaFuncSetAttribute(mma_gemm<3, 1, false>, cudaFuncAttributeMaxDynamicSharedMemorySize, SMTOT3);

    #define SYM(p, s) cudaGetSymbolAddress((void**)&p, s)
    __half *xsh, *xsl, *xoh, *xol, *qth, *qtl, *kth, *ktl, *vh, *vl;
    __half *ph, *pl, *fth, *ftl, *qwh, *qwl, *kvwh, *kvwl, *owh, *owl;
    float *sp, *op, *fp;
    SYM(xsh, g_xs_hi); SYM(xsl, g_xs_lo); SYM(xoh, g_xo_hi); SYM(xol, g_xo_lo);
    SYM(qth, g_qt_hi); SYM(qtl, g_qt_lo); SYM(kth, g_kt_hi); SYM(ktl, g_kt_lo);
    SYM(vh, g_v_hi);   SYM(vl, g_v_lo);   SYM(ph, g_p_hi);   SYM(pl, g_p_lo);
    SYM(fth, g_ft_hi); SYM(ftl, g_ft_lo); SYM(qwh, g_qw_hi); SYM(qwl, g_qw_lo);
    SYM(kvwh, g_kvw_hi); SYM(kvwl, g_kvw_lo); SYM(owh, g_ow_hi); SYM(owl, g_ow_lo);
    SYM(sp, g_attn);   SYM(op, g_o);      SYM(fp, g_fused);
    #undef SYM

    const long long sX = (long long)NPIX * NC;
    const long long sS = (long long)NPIX * NPIX;

    // launch index:      0        1        2          3
    gate_kernel<<<NB, 256>>>(x_self, g1_w, g1_b, g2_w, g2_b);
    wsplit<<<4 * NC * NC / 256, 256>>>(q_w, kv_w, out_w);
    tconv<<<dim3(NPIX / 32, NC / 32, NB), dim3(32, 8)>>>(x_self,  xsh, xsl, NC, NPIX);
    tconv<<<dim3(NPIX / 32, NC / 32, NB), dim3(32, 8)>>>(x_other, xoh, xol, NC, NPIX);

    // 4: Qt[n][o] = sum_c xs[n][c] qw[o][c] + q_b[o]   (fp16 out, col bias) M=4096 N=256
    mma_gemm<3, 2, true><<<dim3(2, 32, NB), 256, SMTOT3>>>(
        xsh, xsl, qwh, qwl, q_b, 1.f, nullptr, qth, qtl, NC, NC, sX, 0, sX);
    // 5 (ncu capture): Kt[m][o] = sum_c xo[m][c] kvw[o][c] + kv_b[o]   M=4096 N=256
    mma_gemm<3, 2, true><<<dim3(2, 32, NB), 256, SMTOT3>>>(
        xoh, xol, kvwh, kvwl, kv_b, 1.f, nullptr, kth, ktl, NC, NC, sX, 0, sX);
    // 6: V[c][n] = sum_k kvw2[c][k] xo[n][k] + kv_b[256+c]   M=256 N=4096 (row bias)
    mma_gemm<3, 1, true><<<dim3(32, 2, NB), 256, SMTOT3>>>(
        kvwh + NC * NC, kvwl + NC * NC, xoh, xol, kv_b + NC, 1.f,
        nullptr, vh, vl, NC, NPIX, 0, sX, sX);
    // 7: S[n][m] = (1/16) sum_c Qt[n][c] Kt[m][c]   M=N=4096 (fp32 out, 2-term)
    mma_gemm<2, 0, false><<<dim3(32, 32, NB), 256, SMTOT2>>>(
        qth, qtl, kth, ktl, nullptr, 0.0625f, sp, nullptr, nullptr, NC, NPIX, sX, sX, sS);

    softmax_rows<<<NB * NPIX, 256>>>();

    // O[n][c] = sum_m P[n][m] V[c][m]   M=4096 N=256 (fp32 out, 2-term)
    mma_gemm<2, 0, false><<<dim3(2, 32, NB), 256, SMTOT2>>>(
        ph, pl, vh, vl, nullptr, 1.f, op, nullptr, nullptr, NPIX, NC, sS, sX, sX);

    fuse_kernel<<<NB * NC, 256>>>(x_self, dw_w, dw_b, bn_g, bn_b, bn_m, bn_v);
    tconv<<<dim3(NPIX / 32, NC / 32, NB), dim3(32, 8)>>>(fp, fth, ftl, NC, NPIX);

    // out[o][n] = sum_c ow[o][c] ft[n][c] + out_b[o]   M=256 N=4096 (fp32, row bias, 3-term)
    mma_gemm<3, 1, false><<<dim3(32, 2, NB), 256, SMTOT3>>>(
        owh, owl, fth, ftl, out_b, 1.f, out, nullptr, nullptr, NC, NPIX, 0, sX, sX);
}

// round 8
// speedup vs baseline: 1.8778x; 1.4784x over previous
#include <cuda_runtime.h>
#include <cuda_fp16.h>
#include <cstdint>
#include <math.h>

#define NB   4
#define NC   256
#define NPIX 4096

// ================= scratch (no allocations allowed) =================
__device__ __align__(128) __half g_xs_hi[(size_t)NB*NPIX*NC];
__device__ __align__(128) __half g_xs_lo[(size_t)NB*NPIX*NC];
__device__ __align__(128) __half g_xo_hi[(size_t)NB*NPIX*NC];
__device__ __align__(128) __half g_xo_lo[(size_t)NB*NPIX*NC];
__device__ __align__(128) __half g_qt_hi[(size_t)NB*NPIX*NC];   // Q^T [n][c] fp16
__device__ __align__(128) __half g_kt_hi[(size_t)NB*NPIX*NC];   // K^T [m][c] fp16
__device__ __align__(128) __half g_v_hi [(size_t)NB*NC*NPIX];   // V [c][m] fp16
__device__ __align__(128) __half g_p    [(size_t)NB*NPIX*NPIX]; // S then P [n][m] fp16 (in-place)
__device__ __align__(128) float  g_o    [(size_t)NB*NPIX*NC];   // O [n][c] fp32
__device__ __align__(128) float  g_fused[(size_t)NB*NC*NPIX];   // fused [c][n] fp32
__device__ __align__(128) __half g_ft_hi[(size_t)NB*NPIX*NC];   // fused^T [n][c]
__device__ __align__(128) __half g_ft_lo[(size_t)NB*NPIX*NC];
__device__ __align__(128) __half g_qw_hi[NC*NC],   g_qw_lo[NC*NC];
__device__ __align__(128) __half g_kvw_hi[2*NC*NC],g_kvw_lo[2*NC*NC];
__device__ __align__(128) __half g_ow_hi[NC*NC],   g_ow_lo[NC*NC];
__device__ float g_gate[NB];

// ================= helpers =================
__device__ __forceinline__ uint32_t smem_u32(const void* p) {
    uint32_t a;
    asm("{ .reg .u64 t; cvta.to.shared.u64 t, %1; cvt.u32.u64 %0, t; }" : "=r"(a) : "l"(p));
    return a;
}
__device__ __forceinline__ void ldm_x4(uint32_t* r, uint32_t addr) {
    asm volatile("ldmatrix.sync.aligned.m8n8.x4.shared.b16 {%0,%1,%2,%3}, [%4];"
        : "=r"(r[0]), "=r"(r[1]), "=r"(r[2]), "=r"(r[3]) : "r"(addr));
}
__device__ __forceinline__ void mma_f16(float* d, const uint32_t* a, uint32_t b0, uint32_t b1) {
    asm volatile("mma.sync.aligned.m16n8k16.row.col.f32.f16.f16.f32 "
        "{%0,%1,%2,%3}, {%4,%5,%6,%7}, {%8,%9}, {%0,%1,%2,%3};"
        : "+f"(d[0]), "+f"(d[1]), "+f"(d[2]), "+f"(d[3])
        : "r"(a[0]), "r"(a[1]), "r"(a[2]), "r"(a[3]), "r"(b0), "r"(b1));
}
#define CP_ASYNC16(saddr, gptr) \
    asm volatile("cp.async.cg.shared.global [%0], [%1], 16;" :: "r"(saddr), "l"(gptr))
#define CP_COMMIT() asm volatile("cp.async.commit_group;" ::: "memory")
#define CP_WAIT0()  asm volatile("cp.async.wait_group 0;" ::: "memory")

__device__ __forceinline__ uint32_t swz(uint32_t o) { return o ^ ((o >> 3) & 0x70); }

__device__ __forceinline__ void split2(float v, __half& h, __half& l) {
    h = __float2half(v);
    l = __float2half(v - __half2float(h));
}

// ================= mma.sync GEMM: D[m][n] = alpha*sum_k A[m][k]*B[n][k] + bias =================
// fp16 K-major operands (row stride = K).
// NTERMS=1: C = Ah*Bh                (both operands fp16-quantized)
// NTERMS=2: C = Ah*Bh + Al*Bh       (A exact to ~2^-24, B quantized)
// CTA tile 128x128, warp tile 32x64 (4x2 warps), K-chunks of 64, double-buffered cp.async.
// BIAS_MODE: 0 none, 1 per-row (M), 2 per-col (N).
// OUT_MODE:  0 fp32, 2 fp16 (hi only).
#define A_TILE  16384                         // 128 rows x 128 bytes
#define SMTOT1  (2 * 2 * A_TILE)              // 65536  (AH BH)
#define SMTOT2  (2 * 3 * A_TILE)              // 98304  (AH AL BH)

__device__ __forceinline__ void cp_tile(uint32_t dst, const __half* src, int K, int tid) {
    #pragma unroll
    for (int r = 0; r < 4; r++) {
        int idx = tid + (r << 8);
        int row = idx >> 3, cc = idx & 7;
        CP_ASYNC16(dst + swz(row * 128 + cc * 16), src + (size_t)row * K + cc * 8);
    }
}

template<int NTERMS, int BIAS_MODE, int OUT_MODE>
__global__ __launch_bounds__(256, 2)
void mma_gemm(const __half* __restrict__ Ah, const __half* __restrict__ Al,
              const __half* __restrict__ Bh,
              const float* __restrict__ bias, float alpha,
              float* __restrict__ Cf, __half* __restrict__ Ch,
              int K, int ldc, long long sA, long long sB, long long sC)
{
    constexpr uint32_t STG = (NTERMS + 1) * A_TILE;
    extern __shared__ __align__(1024) char dsm[];
    const uint32_t sb = smem_u32(dsm);
    const int tid = threadIdx.x, wid = tid >> 5, lane = tid & 31;
    const int warp_m = wid & 3, warp_n = wid >> 2;     // 4 x 2 warps, warp tile 32x64

    const size_t m0 = (size_t)blockIdx.y << 7;
    const size_t n0 = (size_t)blockIdx.x << 7;
    const __half* pah = Ah + (long long)blockIdx.z * sA + m0 * K;
    const __half* pal = (NTERMS == 2) ? (Al + (long long)blockIdx.z * sA + m0 * K) : nullptr;
    const __half* pbh = Bh + (long long)blockIdx.z * sB + n0 * K;

    float acc[2][8][4];
    #pragma unroll
    for (int i = 0; i < 2; i++)
        #pragma unroll
        for (int j = 0; j < 8; j++)
            #pragma unroll
            for (int q = 0; q < 4; q++) acc[i][j][q] = 0.f;

    const uint32_t BH_OFF = NTERMS * A_TILE;
    const int nch = K >> 6;
    cp_tile(sb, pah, K, tid);
    if (NTERMS == 2) cp_tile(sb + A_TILE, pal, K, tid);
    cp_tile(sb + BH_OFF, pbh, K, tid);
    CP_COMMIT();

    for (int ch = 0; ch < nch; ch++) {
        CP_WAIT0();
        __syncthreads();
        if (ch + 1 < nch) {
            const size_t k0 = (size_t)(ch + 1) << 6;
            const uint32_t nb = sb + ((ch + 1) & 1) * STG;
            cp_tile(nb, pah + k0, K, tid);
            if (NTERMS == 2) cp_tile(nb + A_TILE, pal + k0, K, tid);
            cp_tile(nb + BH_OFF, pbh + k0, K, tid);
            CP_COMMIT();
        }
        const uint32_t cbAH = sb + (ch & 1) * STG;
        const uint32_t cbAL = cbAH + A_TILE;
        const uint32_t cbBH = cbAH + BH_OFF;

        #pragma unroll
        for (int ks = 0; ks < 4; ks++) {
            const uint32_t koff = ks * 32 + (lane >> 4) * 16;
            uint32_t a_hi[2][4], a_lo[2][4];
            #pragma unroll
            for (int im = 0; im < 2; im++) {
                uint32_t off = swz((warp_m * 32 + im * 16 + (lane & 15)) * 128 + koff);
                ldm_x4(a_hi[im], cbAH + off);
                if (NTERMS == 2) ldm_x4(a_lo[im], cbAL + off);
            }
            #pragma unroll
            for (int in2 = 0; in2 < 4; in2++) {
                uint32_t off = swz((warp_n * 64 + in2 * 16 + (lane & 15)) * 128 + koff);
                uint32_t bh[4];
                ldm_x4(bh, cbBH + off);
                #pragma unroll
                for (int im = 0; im < 2; im++) {
                    #pragma unroll
                    for (int s = 0; s < 2; s++) {
                        float* d = acc[im][in2 * 2 + s];
                        mma_f16(d, a_hi[im], bh[s], bh[s + 2]);
                        if (NTERMS == 2) mma_f16(d, a_lo[im], bh[s], bh[s + 2]);
                    }
                }
            }
        }
        __syncthreads();
    }

    // ---------------- epilogue ----------------
    const long long cbase = (long long)blockIdx.z * sC;
    #pragma unroll
    for (int im = 0; im < 2; im++) {
        const int r0 = (int)m0 + warp_m * 32 + im * 16 + (lane >> 2);
        const int r1 = r0 + 8;
        float rb0 = 0.f, rb1 = 0.f;
        if (BIAS_MODE == 1) { rb0 = bias[r0]; rb1 = bias[r1]; }
        #pragma unroll
        for (int in = 0; in < 8; in++) {
            const int c = (int)n0 + warp_n * 64 + in * 8 + (lane & 3) * 2;
            float cb0 = rb0, cb1 = rb0, cb2 = rb1, cb3 = rb1;
            if (BIAS_MODE == 2) { cb0 = cb2 = bias[c]; cb1 = cb3 = bias[c + 1]; }
            float v0 = fmaf(alpha, acc[im][in][0], cb0);
            float v1 = fmaf(alpha, acc[im][in][1], cb1);
            float v2 = fmaf(alpha, acc[im][in][2], cb2);
            float v3 = fmaf(alpha, acc[im][in][3], cb3);
            if (OUT_MODE == 2) {
                *reinterpret_cast<__half2*>(Ch + cbase + (size_t)r0 * ldc + c) =
                    __halves2half2(__float2half(v0), __float2half(v1));
                *reinterpret_cast<__half2*>(Ch + cbase + (size_t)r1 * ldc + c) =
                    __halves2half2(__float2half(v2), __float2half(v3));
            } else {
                *reinterpret_cast<float2*>(Cf + cbase + (size_t)r0 * ldc + c) = make_float2(v0, v1);
                *reinterpret_cast<float2*>(Cf + cbase + (size_t)r1 * ldc + c) = make_float2(v2, v3);
            }
        }
    }
}

// ================= transpose + split: src fp32 [R][C] -> dst hi/lo fp16 [C][R] =================
__global__ void tconv(const float* __restrict__ src, __half* __restrict__ dh,
                      __half* __restrict__ dl, int R, int C)
{
    src += (size_t)blockIdx.z * R * C;
    dh  += (size_t)blockIdx.z * R * C;
    dl  += (size_t)blockIdx.z * R * C;
    __shared__ float t[32][33];
    const int c0 = blockIdx.x * 32, r0 = blockIdx.y * 32;
    const int tx = threadIdx.x, ty = threadIdx.y;
    #pragma unroll
    for (int i = 0; i < 4; i++)
        t[ty + 8 * i][tx] = src[(size_t)(r0 + ty + 8 * i) * C + c0 + tx];
    __syncthreads();
    #pragma unroll
    for (int i = 0; i < 4; i++) {
        float v = t[tx][ty + 8 * i];
        size_t o = (size_t)(c0 + ty + 8 * i) * R + r0 + tx;
        __half h, l; split2(v, h, l);
        dh[o] = h; dl[o] = l;
    }
}

// ================= combined weight split =================
__global__ void wsplit(const float* __restrict__ qw, const float* __restrict__ kvw,
                       const float* __restrict__ ow)
{
    int i = blockIdx.x * 256 + threadIdx.x;   // 0 .. 262143
    const float* src; __half *dh, *dl; int off;
    if (i < NC * NC)            { src = qw;  dh = g_qw_hi;  dl = g_qw_lo;  off = i; }
    else if (i < 3 * NC * NC)   { src = kvw; dh = g_kvw_hi; dl = g_kvw_lo; off = i - NC * NC; }
    else                        { src = ow;  dh = g_ow_hi;  dl = g_ow_lo;  off = i - 3 * NC * NC; }
    __half h, l; split2(src[off], h, l);
    dh[off] = h; dl[off] = l;
}

// ================= softmax in-place on fp16 S rows -> P fp16 =================
__global__ __launch_bounds__(256)
void softmax_rows()
{
    __half* row = g_p + (size_t)blockIdx.x * NPIX;
    const int tid = threadIdx.x;
    float4* r4 = reinterpret_cast<float4*>(row);
    float v[16];
    #pragma unroll
    for (int i = 0; i < 2; i++) {
        float4 q = r4[tid + (i << 8)];
        const __half2* hp = reinterpret_cast<const __half2*>(&q);
        #pragma unroll
        for (int j = 0; j < 4; j++) {
            float2 f = __half22float2(hp[j]);
            v[i * 8 + j * 2]     = f.x;
            v[i * 8 + j * 2 + 1] = f.y;
        }
    }

    float m = v[0];
    #pragma unroll
    for (int i = 1; i < 16; i++) m = fmaxf(m, v[i]);
    #pragma unroll
    for (int o = 16; o; o >>= 1) m = fmaxf(m, __shfl_xor_sync(0xffffffffu, m, o));
    __shared__ float sm[8], ss[8];
    if ((tid & 31) == 0) sm[tid >> 5] = m;
    __syncthreads();
    #pragma unroll
    for (int w = 0; w < 8; w++) m = fmaxf(m, sm[w]);

    float s = 0.f;
    #pragma unroll
    for (int i = 0; i < 16; i++) { v[i] = __expf(v[i] - m); s += v[i]; }
    #pragma unroll
    for (int o = 16; o; o >>= 1) s += __shfl_xor_sync(0xffffffffu, s, o);
    if ((tid & 31) == 0) ss[tid >> 5] = s;
    __syncthreads();
    s = 0.f;
    #pragma unroll
    for (int w = 0; w < 8; w++) s += ss[w];

    const float r = 1.f / s;
    #pragma unroll
    for (int i = 0; i < 2; i++) {
        float4 q;
        __half2* hp = reinterpret_cast<__half2*>(&q);
        #pragma unroll
        for (int j = 0; j < 4; j++)
            hp[j] = __floats2half2_rn(v[i * 8 + j * 2] * r, v[i * 8 + j * 2 + 1] * r);
        r4[tid + (i << 8)] = q;
    }
}

// ================= gate MLP =================
__global__ __launch_bounds__(256)
void gate_kernel(const float* __restrict__ xs,
                 const float* __restrict__ g1w, const float* __restrict__ g1b,
                 const float* __restrict__ g2w, const float* __restrict__ g2b)
{
    const int b = blockIdx.x, tid = threadIdx.x;
    const int wid = tid >> 5, lane = tid & 31;
    __shared__ float p[NC];
    const float* x = xs + (size_t)b * NC * NPIX;
    for (int c = wid; c < NC; c += 8) {
        const float* xc = x + (size_t)c * NPIX;
        float s = 0.f;
        for (int i = lane; i < NPIX; i += 32) s += xc[i];
        #pragma unroll
        for (int o = 16; o; o >>= 1) s += __shfl_xor_sync(0xffffffffu, s, o);
        if (!lane) p[c] = s * (1.0f / NPIX);
    }
    __syncthreads();
    __shared__ float hbuf[64];
    if (tid < 64) {
        float s = g1b[tid];
        for (int c = 0; c < NC; c++) s = fmaf(g1w[tid * NC + c], p[c], s);
        hbuf[tid] = fmaxf(s, 0.f);
    }
    __syncthreads();
    if (tid == 0) {
        float s = g2b[0];
        #pragma unroll
        for (int o = 0; o < 64; o++) s = fmaf(g2w[o], hbuf[o], s);
        g_gate[b] = 1.f / (1.f + __expf(-s));
    }
}

// ================= dwconv3x3 + BN + SiLU + gate*O -> fused [c][n] =================
__global__ __launch_bounds__(256)
void fuse_kernel(const float* __restrict__ xs,
                 const float* __restrict__ dww, const float* __restrict__ dwb,
                 const float* __restrict__ bng, const float* __restrict__ bnb,
                 const float* __restrict__ bnm, const float* __restrict__ bnv)
{
    const int bc = blockIdx.x;
    const int b = bc >> 8, c = bc & 255;
    const int tid = threadIdx.x;
    __shared__ float t[66 * 66];
    const float* x = xs + (size_t)bc * NPIX;
    for (int i = tid; i < 66 * 66; i += 256) {
        int h = i / 66 - 1, w = i % 66 - 1;
        t[i] = (h >= 0 && h < 64 && w >= 0 && w < 64) ? x[h * 64 + w] : 0.f;
    }
    float wt[9];
    #pragma unroll
    for (int k = 0; k < 9; k++) wt[k] = dww[c * 9 + k];
    float scale = bng[c] * rsqrtf(bnv[c] + 1e-5f);
    float shift = fmaf(dwb[c] - bnm[c], scale, bnb[c]);
    float gate = g_gate[b];
    float* fptr = g_fused + (size_t)bc * NPIX;
    const float* optr = g_o + (size_t)b * NPIX * NC;   // [n][c]
    __syncthreads();
    for (int i = tid; i < NPIX; i += 256) {
        int h = i >> 6, w = i & 63;
        const float* tp = &t[h * 66 + w];
        float conv = tp[0]   * wt[0] + tp[1]   * wt[1] + tp[2]   * wt[2]
                   + tp[66]  * wt[3] + tp[67]  * wt[4] + tp[68]  * wt[5]
                   + tp[132] * wt[6] + tp[133] * wt[7] + tp[134] * wt[8];
        float y = fmaf(conv, scale, shift);
        float lf = y / (1.f + __expf(-y));
        fptr[i] = fmaf(gate, optr[(size_t)i * NC + c], lf);
    }
}

// ================= launch =================
extern "C" void kernel_launch(void* const* d_in, const int* in_sizes, int n_in,
                              void* d_out, int out_size)
{
    const float* x_self  = (const float*)d_in[0];
    const float* x_other = (const float*)d_in[1];
    const float* q_w  = (const float*)d_in[2];
    const float* q_b  = (const float*)d_in[3];
    const float* kv_w = (const float*)d_in[4];
    const float* kv_b = (const float*)d_in[5];
    const float* g1_w = (const float*)d_in[6];
    const float* g1_b = (const float*)d_in[7];
    const float* g2_w = (const float*)d_in[8];
    const float* g2_b = (const float*)d_in[9];
    const float* dw_w = (const float*)d_in[10];
    const float* dw_b = (const float*)d_in[11];
    const float* bn_g = (const float*)d_in[12];
    const float* bn_b = (const float*)d_in[13];
    const float* bn_m = (const float*)d_in[14];
    const float* bn_v = (const float*)d_in[15];
    const float* out_w = (const float*)d_in[16];
    const float* out_b = (const float*)d_in[17];
    float* out = (float*)d_out;

    cudaFuncSetAttribute(mma_gemm<2, 2, 2>, cudaFuncAttributeMaxDynamicSharedMemorySize, SMTOT2);
    cudaFuncSetAttribute(mma_gemm<2, 1, 2>, cudaFuncAttributeMaxDynamicSharedMemorySize, SMTOT2);
    cudaFuncSetAttribute(mma_gemm<1, 0, 2>, cudaFuncAttributeMaxDynamicSharedMemorySize, SMTOT1);
    cudaFuncSetAttribute(mma_gemm<1, 0, 0>, cudaFuncAttributeMaxDynamicSharedMemorySize, SMTOT1);
    cudaFuncSetAttribute(mma_gemm<2, 1, 0>, cudaFuncAttributeMaxDynamicSharedMemorySize, SMTOT2);

    #define SYM(p, s) cudaGetSymbolAddress((void**)&p, s)
    __half *xsh, *xsl, *xoh, *xol, *qth, *kth, *vh;
    __half *ph, *fth, *ftl, *qwh, *qwl, *kvwh, *kvwl, *owh, *owl;
    float *op, *fp;
    SYM(xsh, g_xs_hi); SYM(xsl, g_xs_lo); SYM(xoh, g_xo_hi); SYM(xol, g_xo_lo);
    SYM(qth, g_qt_hi); SYM(kth, g_kt_hi); SYM(vh, g_v_hi);   SYM(ph, g_p);
    SYM(fth, g_ft_hi); SYM(ftl, g_ft_lo); SYM(qwh, g_qw_hi); SYM(qwl, g_qw_lo);
    SYM(kvwh, g_kvw_hi); SYM(kvwl, g_kvw_lo); SYM(owh, g_ow_hi); SYM(owl, g_ow_lo);
    SYM(op, g_o); SYM(fp, g_fused);
    #undef SYM

    const long long sX = (long long)NPIX * NC;
    const long long sS = (long long)NPIX * NPIX;

    gate_kernel<<<NB, 256>>>(x_self, g1_w, g1_b, g2_w, g2_b);
    wsplit<<<4 * NC * NC / 256, 256>>>(q_w, kv_w, out_w);
    tconv<<<dim3(NPIX / 32, NC / 32, NB), dim3(32, 8)>>>(x_self,  xsh, xsl, NC, NPIX);
    tconv<<<dim3(NPIX / 32, NC / 32, NB), dim3(32, 8)>>>(x_other, xoh, xol, NC, NPIX);

    // Qt[n][o] = sum_c xs[n][c] qw[o][c] + q_b[o]   (fp16 out, col bias, 2-term)
    mma_gemm<2, 2, 2><<<dim3(2, 32, NB), 256, SMTOT2>>>(
        xsh, xsl, qwh, q_b, 1.f, nullptr, qth, NC, NC, sX, 0, sX);
    // Kt[m][o] = sum_c xo[m][c] kvw[o][c] + kv_b[o]
    mma_gemm<2, 2, 2><<<dim3(2, 32, NB), 256, SMTOT2>>>(
        xoh, xol, kvwh, kv_b, 1.f, nullptr, kth, NC, NC, sX, 0, sX);
    // V[c][n] = sum_k kvw2[c][k] xo[n][k] + kv_b[256+c]   (fp16 out, row bias, 2-term)
    mma_gemm<2, 1, 2><<<dim3(32, 2, NB), 256, SMTOT2>>>(
        kvwh + NC * NC, kvwl + NC * NC, xoh, kv_b + NC, 1.f,
        nullptr, vh, NC, NPIX, 0, sX, sX);
    // S[n][m] = (1/16) sum_c Qt[n][c] Kt[m][c]   (fp16 out, 1-term)
    mma_gemm<1, 0, 2><<<dim3(32, 32, NB), 256, SMTOT1>>>(
        qth, nullptr, kth, nullptr, 0.0625f, nullptr, ph, NC, NPIX, sX, sX, sS);

    softmax_rows<<<NB * NPIX, 256>>>();

    // O[n][c] = sum_m P[n][m] V[c][m]   (fp32 out, 1-term)
    mma_gemm<1, 0, 0><<<dim3(2, 32, NB), 256, SMTOT1>>>(
        ph, nullptr, vh, nullptr, 1.f, op, nullptr, NPIX, NC, sS, sX, sX);

    fuse_kernel<<<NB * NC, 256>>>(x_self, dw_w, dw_b, bn_g, bn_b, bn_m, bn_v);
    tconv<<<dim3(NPIX / 32, NC / 32, NB), dim3(32, 8)>>>(fp, fth, ftl, NC, NPIX);

    // out[o][n] = sum_c ow[o][c] ft[n][c] + out_b[o]   (fp32, row bias, 2-term)
    mma_gemm<2, 1, 0><<<dim3(32, 2, NB), 256, SMTOT2>>>(
        owh, owl, fth, out_b, 1.f, out, nullptr, NC, NPIX, 0, sX, sX);
}

// round 9
// speedup vs baseline: 2.4469x; 1.3030x over previous
#include <cuda_runtime.h>
#include <cuda_fp16.h>
#include <cstdint>
#include <math.h>

#define NB   4
#define NC   256
#define NPIX 4096

// ================= scratch (no allocations allowed) =================
__device__ __align__(128) __half g_xs_hi[(size_t)NB*NPIX*NC];
__device__ __align__(128) __half g_xs_lo[(size_t)NB*NPIX*NC];
__device__ __align__(128) __half g_xo_hi[(size_t)NB*NPIX*NC];
__device__ __align__(128) __half g_xo_lo[(size_t)NB*NPIX*NC];
__device__ __align__(128) __half g_qt_hi[(size_t)NB*NPIX*NC];   // Q^T [n][c] fp16
__device__ __align__(128) __half g_kt_hi[(size_t)NB*NPIX*NC];   // K^T [m][c] fp16
__device__ __align__(128) __half g_v_hi [(size_t)NB*NC*NPIX];   // V [c][m] fp16
__device__ __align__(128) __half g_p    [(size_t)NB*NPIX*NPIX]; // S then P [n][m] fp16 (in-place)
__device__ __align__(128) float  g_o    [(size_t)NB*NPIX*NC];   // O [n][c] fp32
__device__ __align__(128) float  g_fused[(size_t)NB*NC*NPIX];   // fused [c][n] fp32
__device__ __align__(128) __half g_ft_hi[(size_t)NB*NPIX*NC];   // fused^T [n][c]
__device__ __align__(128) __half g_ft_lo[(size_t)NB*NPIX*NC];
__device__ __align__(128) __half g_qw_hi[NC*NC],   g_qw_lo[NC*NC];
__device__ __align__(128) __half g_kvw_hi[2*NC*NC],g_kvw_lo[2*NC*NC];
__device__ __align__(128) __half g_ow_hi[NC*NC],   g_ow_lo[NC*NC];
__device__ float g_pool[NB*NC];
__device__ float g_gate[NB];

// ================= helpers =================
__device__ __forceinline__ uint32_t smem_u32(const void* p) {
    uint32_t a;
    asm("{ .reg .u64 t; cvta.to.shared.u64 t, %1; cvt.u32.u64 %0, t; }" : "=r"(a) : "l"(p));
    return a;
}
__device__ __forceinline__ void ldm_x4(uint32_t* r, uint32_t addr) {
    asm volatile("ldmatrix.sync.aligned.m8n8.x4.shared.b16 {%0,%1,%2,%3}, [%4];"
        : "=r"(r[0]), "=r"(r[1]), "=r"(r[2]), "=r"(r[3]) : "r"(addr));
}
__device__ __forceinline__ void mma_f16(float* d, const uint32_t* a, uint32_t b0, uint32_t b1) {
    asm volatile("mma.sync.aligned.m16n8k16.row.col.f32.f16.f16.f32 "
        "{%0,%1,%2,%3}, {%4,%5,%6,%7}, {%8,%9}, {%0,%1,%2,%3};"
        : "+f"(d[0]), "+f"(d[1]), "+f"(d[2]), "+f"(d[3])
        : "r"(a[0]), "r"(a[1]), "r"(a[2]), "r"(a[3]), "r"(b0), "r"(b1));
}
#define CP_ASYNC16(saddr, gptr) \
    asm volatile("cp.async.cg.shared.global [%0], [%1], 16;" :: "r"(saddr), "l"(gptr))
#define CP_COMMIT() asm volatile("cp.async.commit_group;" ::: "memory")
#define CP_WAIT0()  asm volatile("cp.async.wait_group 0;" ::: "memory")

__device__ __forceinline__ uint32_t swz(uint32_t o) { return o ^ ((o >> 3) & 0x70); }

__device__ __forceinline__ void split2(float v, __half& h, __half& l) {
    h = __float2half(v);
    l = __float2half(v - __half2float(h));
}

// ================= mma.sync GEMM: D[m][n] = alpha*sum_k A[m][k]*B[n][k] + bias =================
// fp16 K-major operands (row stride = K).
// NTERMS=1: C = Ah*Bh          NTERMS=2: C = Ah*Bh + Al*Bh
// CTA tile 128x128, warp tile 32x64 (4x2 warps), K-chunks of 64, double-buffered cp.async.
// BIAS_MODE: 0 none, 1 per-row (M), 2 per-col (N).  OUT_MODE: 0 fp32, 2 fp16.
#define A_TILE  16384
#define SMTOT1  (2 * 2 * A_TILE)              // 65536  (AH BH)
#define SMTOT2  (2 * 3 * A_TILE)              // 98304  (AH AL BH)

__device__ __forceinline__ void cp_tile(uint32_t dst, const __half* src, int K, int tid) {
    #pragma unroll
    for (int r = 0; r < 4; r++) {
        int idx = tid + (r << 8);
        int row = idx >> 3, cc = idx & 7;
        CP_ASYNC16(dst + swz(row * 128 + cc * 16), src + (size_t)row * K + cc * 8);
    }
}

template<int NTERMS, int BIAS_MODE, int OUT_MODE>
__global__ __launch_bounds__(256, 2)
void mma_gemm(const __half* __restrict__ Ah, const __half* __restrict__ Al,
              const __half* __restrict__ Bh,
              const float* __restrict__ bias, float alpha,
              float* __restrict__ Cf, __half* __restrict__ Ch,
              int K, int ldc, long long sA, long long sB, long long sC)
{
    constexpr uint32_t STG = (NTERMS + 1) * A_TILE;
    extern __shared__ __align__(1024) char dsm[];
    const uint32_t sb = smem_u32(dsm);
    const int tid = threadIdx.x, wid = tid >> 5, lane = tid & 31;
    const int warp_m = wid & 3, warp_n = wid >> 2;

    const size_t m0 = (size_t)blockIdx.y << 7;
    const size_t n0 = (size_t)blockIdx.x << 7;
    const __half* pah = Ah + (long long)blockIdx.z * sA + m0 * K;
    const __half* pal = (NTERMS == 2) ? (Al + (long long)blockIdx.z * sA + m0 * K) : nullptr;
    const __half* pbh = Bh + (long long)blockIdx.z * sB + n0 * K;

    float acc[2][8][4];
    #pragma unroll
    for (int i = 0; i < 2; i++)
        #pragma unroll
        for (int j = 0; j < 8; j++)
            #pragma unroll
            for (int q = 0; q < 4; q++) acc[i][j][q] = 0.f;

    const uint32_t BH_OFF = NTERMS * A_TILE;
    const int nch = K >> 6;
    cp_tile(sb, pah, K, tid);
    if (NTERMS == 2) cp_tile(sb + A_TILE, pal, K, tid);
    cp_tile(sb + BH_OFF, pbh, K, tid);
    CP_COMMIT();

    for (int ch = 0; ch < nch; ch++) {
        CP_WAIT0();
        __syncthreads();
        if (ch + 1 < nch) {
            const size_t k0 = (size_t)(ch + 1) << 6;
            const uint32_t nb = sb + ((ch + 1) & 1) * STG;
            cp_tile(nb, pah + k0, K, tid);
            if (NTERMS == 2) cp_tile(nb + A_TILE, pal + k0, K, tid);
            cp_tile(nb + BH_OFF, pbh + k0, K, tid);
            CP_COMMIT();
        }
        const uint32_t cbAH = sb + (ch & 1) * STG;
        const uint32_t cbAL = cbAH + A_TILE;
        const uint32_t cbBH = cbAH + BH_OFF;

        #pragma unroll
        for (int ks = 0; ks < 4; ks++) {
            const uint32_t koff = ks * 32 + (lane >> 4) * 16;
            uint32_t a_hi[2][4], a_lo[2][4];
            #pragma unroll
            for (int im = 0; im < 2; im++) {
                uint32_t off = swz((warp_m * 32 + im * 16 + (lane & 15)) * 128 + koff);
                ldm_x4(a_hi[im], cbAH + off);
                if (NTERMS == 2) ldm_x4(a_lo[im], cbAL + off);
            }
            #pragma unroll
            for (int in2 = 0; in2 < 4; in2++) {
                uint32_t off = swz((warp_n * 64 + in2 * 16 + (lane & 15)) * 128 + koff);
                uint32_t bh[4];
                ldm_x4(bh, cbBH + off);
                #pragma unroll
                for (int im = 0; im < 2; im++) {
                    #pragma unroll
                    for (int s = 0; s < 2; s++) {
                        float* d = acc[im][in2 * 2 + s];
                        mma_f16(d, a_hi[im], bh[s], bh[s + 2]);
                        if (NTERMS == 2) mma_f16(d, a_lo[im], bh[s], bh[s + 2]);
                    }
                }
            }
        }
        __syncthreads();
    }

    // ---------------- epilogue ----------------
    const long long cbase = (long long)blockIdx.z * sC;
    #pragma unroll
    for (int im = 0; im < 2; im++) {
        const int r0 = (int)m0 + warp_m * 32 + im * 16 + (lane >> 2);
        const int r1 = r0 + 8;
        float rb0 = 0.f, rb1 = 0.f;
        if (BIAS_MODE == 1) { rb0 = bias[r0]; rb1 = bias[r1]; }
        #pragma unroll
        for (int in = 0; in < 8; in++) {
            const int c = (int)n0 + warp_n * 64 + in * 8 + (lane & 3) * 2;
            float cb0 = rb0, cb1 = rb0, cb2 = rb1, cb3 = rb1;
            if (BIAS_MODE == 2) { cb0 = cb2 = bias[c]; cb1 = cb3 = bias[c + 1]; }
            float v0 = fmaf(alpha, acc[im][in][0], cb0);
            float v1 = fmaf(alpha, acc[im][in][1], cb1);
            float v2 = fmaf(alpha, acc[im][in][2], cb2);
            float v3 = fmaf(alpha, acc[im][in][3], cb3);
            if (OUT_MODE == 2) {
                *reinterpret_cast<__half2*>(Ch + cbase + (size_t)r0 * ldc + c) =
                    __halves2half2(__float2half(v0), __float2half(v1));
                *reinterpret_cast<__half2*>(Ch + cbase + (size_t)r1 * ldc + c) =
                    __halves2half2(__float2half(v2), __float2half(v3));
            } else {
                *reinterpret_cast<float2*>(Cf + cbase + (size_t)r0 * ldc + c) = make_float2(v0, v1);
                *reinterpret_cast<float2*>(Cf + cbase + (size_t)r1 * ldc + c) = make_float2(v2, v3);
            }
        }
    }
}

// ================= transpose + split: src fp32 [R][C] -> dst hi/lo fp16 [C][R] =================
// Tile: 64 src-rows (channels) x 32 src-cols (pixels); half2 stores along channel dim.
__global__ void tconv(const float* __restrict__ src, __half* __restrict__ dh,
                      __half* __restrict__ dl, int R, int C)
{
    src += (size_t)blockIdx.z * R * C;
    dh  += (size_t)blockIdx.z * R * C;
    dl  += (size_t)blockIdx.z * R * C;
    __shared__ float t[64][33];
    const int c0 = blockIdx.x * 32, r0 = blockIdx.y * 64;
    const int tx = threadIdx.x, ty = threadIdx.y;
    #pragma unroll
    for (int i = 0; i < 8; i++)
        t[ty + 8 * i][tx] = src[(size_t)(r0 + ty + 8 * i) * C + c0 + tx];
    __syncthreads();
    #pragma unroll
    for (int i = 0; i < 4; i++) {
        const int pixl = ty + 8 * i;
        float v0 = t[2 * tx][pixl], v1 = t[2 * tx + 1][pixl];
        __half h0, l0, h1, l1;
        split2(v0, h0, l0); split2(v1, h1, l1);
        size_t o = (size_t)(c0 + pixl) * R + r0 + 2 * tx;
        *reinterpret_cast<__half2*>(dh + o) = __halves2half2(h0, h1);
        *reinterpret_cast<__half2*>(dl + o) = __halves2half2(l0, l1);
    }
}

// ================= combined weight split =================
__global__ void wsplit(const float* __restrict__ qw, const float* __restrict__ kvw,
                       const float* __restrict__ ow)
{
    int i = blockIdx.x * 256 + threadIdx.x;
    const float* src; __half *dh, *dl; int off;
    if (i < NC * NC)            { src = qw;  dh = g_qw_hi;  dl = g_qw_lo;  off = i; }
    else if (i < 3 * NC * NC)   { src = kvw; dh = g_kvw_hi; dl = g_kvw_lo; off = i - NC * NC; }
    else                        { src = ow;  dh = g_ow_hi;  dl = g_ow_lo;  off = i - 3 * NC * NC; }
    __half h, l; split2(src[off], h, l);
    dh[off] = h; dl[off] = l;
}

// ================= spatial mean pool: one block per (b, c) =================
__global__ __launch_bounds__(128)
void pool_kernel(const float* __restrict__ xs)
{
    const int c = blockIdx.x, b = blockIdx.y;
    const int tid = threadIdx.x, lane = tid & 31, wid = tid >> 5;
    const float4* x = reinterpret_cast<const float4*>(xs + ((size_t)b * NC + c) * NPIX);
    float s = 0.f;
    #pragma unroll
    for (int i = 0; i < 8; i++) {
        float4 v = x[tid + i * 128];
        s += (v.x + v.y) + (v.z + v.w);
    }
    #pragma unroll
    for (int o = 16; o; o >>= 1) s += __shfl_xor_sync(0xffffffffu, s, o);
    __shared__ float ws[4];
    if (!lane) ws[wid] = s;
    __syncthreads();
    if (tid == 0)
        g_pool[b * NC + c] = (ws[0] + ws[1] + ws[2] + ws[3]) * (1.0f / NPIX);
}

// ================= gate MLP (tiny) =================
__global__ __launch_bounds__(64)
void gate_mlp(const float* __restrict__ g1w, const float* __restrict__ g1b,
              const float* __restrict__ g2w, const float* __restrict__ g2b)
{
    const int b = blockIdx.x, tid = threadIdx.x;
    __shared__ float p[NC];
    for (int c = tid; c < NC; c += 64) p[c] = g_pool[b * NC + c];
    __syncthreads();
    __shared__ float hbuf[64];
    {
        float s = g1b[tid];
        #pragma unroll 4
        for (int c = 0; c < NC; c++) s = fmaf(g1w[tid * NC + c], p[c], s);
        hbuf[tid] = fmaxf(s, 0.f);
    }
    __syncthreads();
    if (tid == 0) {
        float s = g2b[0];
        #pragma unroll
        for (int o = 0; o < 64; o++) s = fmaf(g2w[o], hbuf[o], s);
        g_gate[b] = 1.f / (1.f + __expf(-s));
    }
}

// ================= softmax in-place on fp16 S rows -> P fp16 =================
__global__ __launch_bounds__(256)
void softmax_rows()
{
    __half* row = g_p + (size_t)blockIdx.x * NPIX;
    const int tid = threadIdx.x;
    float4* r4 = reinterpret_cast<float4*>(row);
    float v[16];
    #pragma unroll
    for (int i = 0; i < 2; i++) {
        float4 q = r4[tid + (i << 8)];
        const __half2* hp = reinterpret_cast<const __half2*>(&q);
        #pragma unroll
        for (int j = 0; j < 4; j++) {
            float2 f = __half22float2(hp[j]);
            v[i * 8 + j * 2]     = f.x;
            v[i * 8 + j * 2 + 1] = f.y;
        }
    }

    float m = v[0];
    #pragma unroll
    for (int i = 1; i < 16; i++) m = fmaxf(m, v[i]);
    #pragma unroll
    for (int o = 16; o; o >>= 1) m = fmaxf(m, __shfl_xor_sync(0xffffffffu, m, o));
    __shared__ float sm[8], ss[8];
    if ((tid & 31) == 0) sm[tid >> 5] = m;
    __syncthreads();
    #pragma unroll
    for (int w = 0; w < 8; w++) m = fmaxf(m, sm[w]);

    float s = 0.f;
    #pragma unroll
    for (int i = 0; i < 16; i++) { v[i] = __expf(v[i] - m); s += v[i]; }
    #pragma unroll
    for (int o = 16; o; o >>= 1) s += __shfl_xor_sync(0xffffffffu, s, o);
    if ((tid & 31) == 0) ss[tid >> 5] = s;
    __syncthreads();
    s = 0.f;
    #pragma unroll
    for (int w = 0; w < 8; w++) s += ss[w];

    const float r = 1.f / s;
    #pragma unroll
    for (int i = 0; i < 2; i++) {
        float4 q;
        __half2* hp = reinterpret_cast<__half2*>(&q);
        #pragma unroll
        for (int j = 0; j < 4; j++)
            hp[j] = __floats2half2_rn(v[i * 8 + j * 2] * r, v[i * 8 + j * 2 + 1] * r);
        r4[tid + (i << 8)] = q;
    }
}

// ================= dwconv3x3 + BN + SiLU + gate*O -> fused [c][n] =================
__global__ __launch_bounds__(256)
void fuse_kernel(const float* __restrict__ xs,
                 const float* __restrict__ dww, const float* __restrict__ dwb,
                 const float* __restrict__ bng, const float* __restrict__ bnb,
                 const float* __restrict__ bnm, const float* __restrict__ bnv)
{
    const int bc = blockIdx.x;
    const int b = bc >> 8, c = bc & 255;
    const int tid = threadIdx.x;
    __shared__ float t[66 * 66];
    const float* x = xs + (size_t)bc * NPIX;
    for (int i = tid; i < 66 * 66; i += 256) {
        int h = i / 66 - 1, w = i % 66 - 1;
        t[i] = (h >= 0 && h < 64 && w >= 0 && w < 64) ? x[h * 64 + w] : 0.f;
    }
    float wt[9];
    #pragma unroll
    for (int k = 0; k < 9; k++) wt[k] = dww[c * 9 + k];
    float scale = bng[c] * rsqrtf(bnv[c] + 1e-5f);
    float shift = fmaf(dwb[c] - bnm[c], scale, bnb[c]);
    float gate = g_gate[b];
    float* fptr = g_fused + (size_t)bc * NPIX;
    const float* optr = g_o + (size_t)b * NPIX * NC;   // [n][c]
    __syncthreads();
    for (int i = tid; i < NPIX; i += 256) {
        int h = i >> 6, w = i & 63;
        const float* tp = &t[h * 66 + w];
        float conv = tp[0]   * wt[0] + tp[1]   * wt[1] + tp[2]   * wt[2]
                   + tp[66]  * wt[3] + tp[67]  * wt[4] + tp[68]  * wt[5]
                   + tp[132] * wt[6] + tp[133] * wt[7] + tp[134] * wt[8];
        float y = fmaf(conv, scale, shift);
        float lf = y / (1.f + __expf(-y));
        fptr[i] = fmaf(gate, optr[(size_t)i * NC + c], lf);
    }
}

// ================= launch =================
extern "C" void kernel_launch(void* const* d_in, const int* in_sizes, int n_in,
                              void* d_out, int out_size)
{
    const float* x_self  = (const float*)d_in[0];
    const float* x_other = (const float*)d_in[1];
    const float* q_w  = (const float*)d_in[2];
    const float* q_b  = (const float*)d_in[3];
    const float* kv_w = (const float*)d_in[4];
    const float* kv_b = (const float*)d_in[5];
    const float* g1_w = (const float*)d_in[6];
    const float* g1_b = (const float*)d_in[7];
    const float* g2_w = (const float*)d_in[8];
    const float* g2_b = (const float*)d_in[9];
    const float* dw_w = (const float*)d_in[10];
    const float* dw_b = (const float*)d_in[11];
    const float* bn_g = (const float*)d_in[12];
    const float* bn_b = (const float*)d_in[13];
    const float* bn_m = (const float*)d_in[14];
    const float* bn_v = (const float*)d_in[15];
    const float* out_w = (const float*)d_in[16];
    const float* out_b = (const float*)d_in[17];
    float* out = (float*)d_out;

    cudaFuncSetAttribute(mma_gemm<2, 2, 2>, cudaFuncAttributeMaxDynamicSharedMemorySize, SMTOT2);
    cudaFuncSetAttribute(mma_gemm<2, 1, 2>, cudaFuncAttributeMaxDynamicSharedMemorySize, SMTOT2);
    cudaFuncSetAttribute(mma_gemm<1, 0, 2>, cudaFuncAttributeMaxDynamicSharedMemorySize, SMTOT1);
    cudaFuncSetAttribute(mma_gemm<1, 0, 0>, cudaFuncAttributeMaxDynamicSharedMemorySize, SMTOT1);
    cudaFuncSetAttribute(mma_gemm<2, 1, 0>, cudaFuncAttributeMaxDynamicSharedMemorySize, SMTOT2);

    #define SYM(p, s) cudaGetSymbolAddress((void**)&p, s)
    __half *xsh, *xsl, *xoh, *xol, *qth, *kth, *vh;
    __half *ph, *fth, *ftl, *qwh, *qwl, *kvwh, *kvwl, *owh, *owl;
    float *op, *fp;
    SYM(xsh, g_xs_hi); SYM(xsl, g_xs_lo); SYM(xoh, g_xo_hi); SYM(xol, g_xo_lo);
    SYM(qth, g_qt_hi); SYM(kth, g_kt_hi); SYM(vh, g_v_hi);   SYM(ph, g_p);
    SYM(fth, g_ft_hi); SYM(ftl, g_ft_lo); SYM(qwh, g_qw_hi); SYM(qwl, g_qw_lo);
    SYM(kvwh, g_kvw_hi); SYM(kvwl, g_kvw_lo); SYM(owh, g_ow_hi); SYM(owl, g_ow_lo);
    SYM(op, g_o); SYM(fp, g_fused);
    #undef SYM

    const long long sX = (long long)NPIX * NC;
    const long long sS = (long long)NPIX * NPIX;

    pool_kernel<<<dim3(NC, NB), 128>>>(x_self);
    gate_mlp<<<NB, 64>>>(g1_w, g1_b, g2_w, g2_b);
    wsplit<<<4 * NC * NC / 256, 256>>>(q_w, kv_w, out_w);
    tconv<<<dim3(NPIX / 32, NC / 64, NB), dim3(32, 8)>>>(x_self,  xsh, xsl, NC, NPIX);
    tconv<<<dim3(NPIX / 32, NC / 64, NB), dim3(32, 8)>>>(x_other, xoh, xol, NC, NPIX);

    // Qt[n][o] = sum_c xs[n][c] qw[o][c] + q_b[o]   (fp16 out, col bias, 2-term)
    mma_gemm<2, 2, 2><<<dim3(2, 32, NB), 256, SMTOT2>>>(
        xsh, xsl, qwh, q_b, 1.f, nullptr, qth, NC, NC, sX, 0, sX);
    // Kt[m][o] = sum_c xo[m][c] kvw[o][c] + kv_b[o]
    mma_gemm<2, 2, 2><<<dim3(2, 32, NB), 256, SMTOT2>>>(
        xoh, xol, kvwh, kv_b, 1.f, nullptr, kth, NC, NC, sX, 0, sX);
    // V[c][n] = sum_k kvw2[c][k] xo[n][k] + kv_b[256+c]   (fp16 out, row bias, 2-term)
    mma_gemm<2, 1, 2><<<dim3(32, 2, NB), 256, SMTOT2>>>(
        kvwh + NC * NC, kvwl + NC * NC, xoh, kv_b + NC, 1.f,
        nullptr, vh, NC, NPIX, 0, sX, sX);
    // S[n][m] = (1/16) sum_c Qt[n][c] Kt[m][c]   (fp16 out, 1-term)
    mma_gemm<1, 0, 2><<<dim3(32, 32, NB), 256, SMTOT1>>>(
        qth, nullptr, kth, nullptr, 0.0625f, nullptr, ph, NC, NPIX, sX, sX, sS);

    softmax_rows<<<NB * NPIX, 256>>>();

    // O[n][c] = sum_m P[n][m] V[c][m]   (fp32 out, 1-term)
    mma_gemm<1, 0, 0><<<dim3(2, 32, NB), 256, SMTOT1>>>(
        ph, nullptr, vh, nullptr, 1.f, op, nullptr, NPIX, NC, sS, sX, sX);

    fuse_kernel<<<NB * NC, 256>>>(x_self, dw_w, dw_b, bn_g, bn_b, bn_m, bn_v);
    tconv<<<dim3(NPIX / 32, NC / 64, NB), dim3(32, 8)>>>(fp, fth, ftl, NC, NPIX);

    // out[o][n] = sum_c ow[o][c] ft[n][c] + out_b[o]   (fp32, row bias, 2-term)
    mma_gemm<2, 1, 0><<<dim3(32, 2, NB), 256, SMTOT2>>>(
        owh, owl, fth, out_b, 1.f, out, nullptr, NC, NPIX, 0, sX, sX);
}

// round 10
// speedup vs baseline: 2.6713x; 1.0917x over previous
#include <cuda_runtime.h>
#include <cuda_fp16.h>
#include <cstdint>
#include <math.h>

#define NB   4
#define NC   256
#define NPIX 4096

// ================= scratch (no allocations allowed) =================
__device__ __align__(128) __half g_xs_hi[(size_t)NB*NPIX*NC];   // x_self^T [n][c]
__device__ __align__(128) __half g_xo_hi[(size_t)NB*NPIX*NC];   // x_other^T [n][c]
__device__ __align__(128) __half g_qt_hi[(size_t)NB*NPIX*NC];   // Q^T [n][c]
__device__ __align__(128) __half g_kt_hi[(size_t)NB*NPIX*NC];   // K^T [m][c]
__device__ __align__(128) __half g_v_hi [(size_t)NB*NC*NPIX];   // V [c][m]
__device__ __align__(128) __half g_p    [(size_t)NB*NPIX*NPIX]; // S then P [n][m] (in-place)
__device__ __align__(128) float  g_o    [(size_t)NB*NC*NPIX];   // O^T [c][n] fp32
__device__ __align__(128) float  g_fused[(size_t)NB*NC*NPIX];   // fused [c][n] fp32
__device__ __align__(128) __half g_ft_hi[(size_t)NB*NPIX*NC];   // fused^T [n][c]
__device__ __align__(128) __half g_qw_hi[NC*NC];
__device__ __align__(128) __half g_kvw_hi[2*NC*NC];
__device__ __align__(128) __half g_ow_hi[NC*NC], g_ow_lo[NC*NC];
__device__ float g_pool[NB*NC];
__device__ float g_gate[NB];

// ================= helpers =================
__device__ __forceinline__ uint32_t smem_u32(const void* p) {
    uint32_t a;
    asm("{ .reg .u64 t; cvta.to.shared.u64 t, %1; cvt.u32.u64 %0, t; }" : "=r"(a) : "l"(p));
    return a;
}
__device__ __forceinline__ void ldm_x4(uint32_t* r, uint32_t addr) {
    asm volatile("ldmatrix.sync.aligned.m8n8.x4.shared.b16 {%0,%1,%2,%3}, [%4];"
        : "=r"(r[0]), "=r"(r[1]), "=r"(r[2]), "=r"(r[3]) : "r"(addr));
}
__device__ __forceinline__ void mma_f16(float* d, const uint32_t* a, uint32_t b0, uint32_t b1) {
    asm volatile("mma.sync.aligned.m16n8k16.row.col.f32.f16.f16.f32 "
        "{%0,%1,%2,%3}, {%4,%5,%6,%7}, {%8,%9}, {%0,%1,%2,%3};"
        : "+f"(d[0]), "+f"(d[1]), "+f"(d[2]), "+f"(d[3])
        : "r"(a[0]), "r"(a[1]), "r"(a[2]), "r"(a[3]), "r"(b0), "r"(b1));
}
#define CP_ASYNC16(saddr, gptr) \
    asm volatile("cp.async.cg.shared.global [%0], [%1], 16;" :: "r"(saddr), "l"(gptr))
#define CP_COMMIT() asm volatile("cp.async.commit_group;" ::: "memory")
#define CP_WAIT0()  asm volatile("cp.async.wait_group 0;" ::: "memory")

__device__ __forceinline__ uint32_t swz(uint32_t o) { return o ^ ((o >> 3) & 0x70); }

__device__ __forceinline__ void split2(float v, __half& h, __half& l) {
    h = __float2half(v);
    l = __float2half(v - __half2float(h));
}

// ================= mma.sync GEMM: D[m][n] = alpha*sum_k A[m][k]*B[n][k] + bias =================
// fp16 K-major operands. NTERMS=1: Ah*Bh. NTERMS=2: Ah*Bh + Al*Bh.
// CTA tile 128x128, warp tile 32x64, K-chunks of 64, double-buffered cp.async.
// BIAS_MODE: 0 none, 1 per-row (M), 2 per-col (N).  OUT_MODE: 0 fp32, 2 fp16.
#define A_TILE  16384
#define SMTOT1  (2 * 2 * A_TILE)              // 65536
#define SMTOT2  (2 * 3 * A_TILE)              // 98304

__device__ __forceinline__ void cp_tile(uint32_t dst, const __half* src, int K, int tid) {
    #pragma unroll
    for (int r = 0; r < 4; r++) {
        int idx = tid + (r << 8);
        int row = idx >> 3, cc = idx & 7;
        CP_ASYNC16(dst + swz(row * 128 + cc * 16), src + (size_t)row * K + cc * 8);
    }
}

template<int NTERMS, int BIAS_MODE, int OUT_MODE>
__global__ __launch_bounds__(256, 2)
void mma_gemm(const __half* __restrict__ Ah, const __half* __restrict__ Al,
              const __half* __restrict__ Bh,
              const float* __restrict__ bias, float alpha,
              float* __restrict__ Cf, __half* __restrict__ Ch,
              int K, int ldc, long long sA, long long sB, long long sC)
{
    constexpr uint32_t STG = (NTERMS + 1) * A_TILE;
    extern __shared__ __align__(1024) char dsm[];
    const uint32_t sb = smem_u32(dsm);
    const int tid = threadIdx.x, wid = tid >> 5, lane = tid & 31;
    const int warp_m = wid & 3, warp_n = wid >> 2;

    const size_t m0 = (size_t)blockIdx.y << 7;
    const size_t n0 = (size_t)blockIdx.x << 7;
    const __half* pah = Ah + (long long)blockIdx.z * sA + m0 * K;
    const __half* pal = (NTERMS == 2) ? (Al + (long long)blockIdx.z * sA + m0 * K) : nullptr;
    const __half* pbh = Bh + (long long)blockIdx.z * sB + n0 * K;

    float acc[2][8][4];
    #pragma unroll
    for (int i = 0; i < 2; i++)
        #pragma unroll
        for (int j = 0; j < 8; j++)
            #pragma unroll
            for (int q = 0; q < 4; q++) acc[i][j][q] = 0.f;

    const uint32_t BH_OFF = NTERMS * A_TILE;
    const int nch = K >> 6;
    cp_tile(sb, pah, K, tid);
    if (NTERMS == 2) cp_tile(sb + A_TILE, pal, K, tid);
    cp_tile(sb + BH_OFF, pbh, K, tid);
    CP_COMMIT();

    for (int ch = 0; ch < nch; ch++) {
        CP_WAIT0();
        __syncthreads();
        if (ch + 1 < nch) {
            const size_t k0 = (size_t)(ch + 1) << 6;
            const uint32_t nb = sb + ((ch + 1) & 1) * STG;
            cp_tile(nb, pah + k0, K, tid);
            if (NTERMS == 2) cp_tile(nb + A_TILE, pal + k0, K, tid);
            cp_tile(nb + BH_OFF, pbh + k0, K, tid);
            CP_COMMIT();
        }
        const uint32_t cbAH = sb + (ch & 1) * STG;
        const uint32_t cbAL = cbAH + A_TILE;
        const uint32_t cbBH = cbAH + BH_OFF;

        #pragma unroll
        for (int ks = 0; ks < 4; ks++) {
            const uint32_t koff = ks * 32 + (lane >> 4) * 16;
            uint32_t a_hi[2][4], a_lo[2][4];
            #pragma unroll
            for (int im = 0; im < 2; im++) {
                uint32_t off = swz((warp_m * 32 + im * 16 + (lane & 15)) * 128 + koff);
                ldm_x4(a_hi[im], cbAH + off);
                if (NTERMS == 2) ldm_x4(a_lo[im], cbAL + off);
            }
            #pragma unroll
            for (int in2 = 0; in2 < 4; in2++) {
                uint32_t off = swz((warp_n * 64 + in2 * 16 + (lane & 15)) * 128 + koff);
                uint32_t bh[4];
                ldm_x4(bh, cbBH + off);
                #pragma unroll
                for (int im = 0; im < 2; im++) {
                    #pragma unroll
                    for (int s = 0; s < 2; s++) {
                        float* d = acc[im][in2 * 2 + s];
                        mma_f16(d, a_hi[im], bh[s], bh[s + 2]);
                        if (NTERMS == 2) mma_f16(d, a_lo[im], bh[s], bh[s + 2]);
                    }
                }
            }
        }
        __syncthreads();
    }

    // ---------------- epilogue ----------------
    const long long cbase = (long long)blockIdx.z * sC;
    #pragma unroll
    for (int im = 0; im < 2; im++) {
        const int r0 = (int)m0 + warp_m * 32 + im * 16 + (lane >> 2);
        const int r1 = r0 + 8;
        float rb0 = 0.f, rb1 = 0.f;
        if (BIAS_MODE == 1) { rb0 = bias[r0]; rb1 = bias[r1]; }
        #pragma unroll
        for (int in = 0; in < 8; in++) {
            const int c = (int)n0 + warp_n * 64 + in * 8 + (lane & 3) * 2;
            float cb0 = rb0, cb1 = rb0, cb2 = rb1, cb3 = rb1;
            if (BIAS_MODE == 2) { cb0 = cb2 = bias[c]; cb1 = cb3 = bias[c + 1]; }
            float v0 = fmaf(alpha, acc[im][in][0], cb0);
            float v1 = fmaf(alpha, acc[im][in][1], cb1);
            float v2 = fmaf(alpha, acc[im][in][2], cb2);
            float v3 = fmaf(alpha, acc[im][in][3], cb3);
            if (OUT_MODE == 2) {
                *reinterpret_cast<__half2*>(Ch + cbase + (size_t)r0 * ldc + c) =
                    __halves2half2(__float2half(v0), __float2half(v1));
                *reinterpret_cast<__half2*>(Ch + cbase + (size_t)r1 * ldc + c) =
                    __halves2half2(__float2half(v2), __float2half(v3));
            } else {
                *reinterpret_cast<float2*>(Cf + cbase + (size_t)r0 * ldc + c) = make_float2(v0, v1);
                *reinterpret_cast<float2*>(Cf + cbase + (size_t)r1 * ldc + c) = make_float2(v2, v3);
            }
        }
    }
}

// ================= transpose + fp16 convert (hi only) =================
// Tile: 64 src-rows x 32 src-cols; half2 stores along channel dim.
__device__ __forceinline__ void tconv_body(const float* src, __half* dh, int R, int C) {
    __shared__ float t[64][33];
    const int c0 = blockIdx.x * 32, r0 = blockIdx.y * 64;
    const int tx = threadIdx.x, ty = threadIdx.y;
    #pragma unroll
    for (int i = 0; i < 8; i++)
        t[ty + 8 * i][tx] = src[(size_t)(r0 + ty + 8 * i) * C + c0 + tx];
    __syncthreads();
    #pragma unroll
    for (int i = 0; i < 4; i++) {
        const int pixl = ty + 8 * i;
        size_t o = (size_t)(c0 + pixl) * R + r0 + 2 * tx;
        *reinterpret_cast<__half2*>(dh + o) =
            __floats2half2_rn(t[2 * tx][pixl], t[2 * tx + 1][pixl]);
    }
}

// paired: z = b*2 + sel  (xs / xo in one launch)
__global__ void tconv_pair(const float* __restrict__ sA, __half* __restrict__ dA,
                           const float* __restrict__ sB, __half* __restrict__ dB,
                           int R, int C)
{
    const int sel = blockIdx.z & 1, b = blockIdx.z >> 1;
    const float* src = (sel ? sB : sA) + (size_t)b * R * C;
    __half* dh = (sel ? dB : dA) + (size_t)b * R * C;
    tconv_body(src, dh, R, C);
}

__global__ void tconv1(const float* __restrict__ s, __half* __restrict__ d, int R, int C)
{
    tconv_body(s + (size_t)blockIdx.z * R * C, d + (size_t)blockIdx.z * R * C, R, C);
}

// ================= weight split: qw hi, kvw hi, ow hi+lo =================
__global__ void wsplit(const float* __restrict__ qw, const float* __restrict__ kvw,
                       const float* __restrict__ ow)
{
    int i = blockIdx.x * 256 + threadIdx.x;   // 0 .. 262143
    if (i < NC * NC) {
        g_qw_hi[i] = __float2half(qw[i]);
    } else if (i < 3 * NC * NC) {
        int off = i - NC * NC;
        g_kvw_hi[off] = __float2half(kvw[off]);
    } else {
        int off = i - 3 * NC * NC;
        __half h, l; split2(ow[off], h, l);
        g_ow_hi[off] = h; g_ow_lo[off] = l;
    }
}

// ================= spatial mean pool: one block per (b, c) =================
__global__ __launch_bounds__(128)
void pool_kernel(const float* __restrict__ xs)
{
    const int c = blockIdx.x, b = blockIdx.y;
    const int tid = threadIdx.x, lane = tid & 31, wid = tid >> 5;
    const float4* x = reinterpret_cast<const float4*>(xs + ((size_t)b * NC + c) * NPIX);
    float s = 0.f;
    #pragma unroll
    for (int i = 0; i < 8; i++) {
        float4 v = x[tid + i * 128];
        s += (v.x + v.y) + (v.z + v.w);
    }
    #pragma unroll
    for (int o = 16; o; o >>= 1) s += __shfl_xor_sync(0xffffffffu, s, o);
    __shared__ float ws[4];
    if (!lane) ws[wid] = s;
    __syncthreads();
    if (tid == 0)
        g_pool[b * NC + c] = (ws[0] + ws[1] + ws[2] + ws[3]) * (1.0f / NPIX);
}

// ================= gate MLP (tiny) =================
__global__ __launch_bounds__(64)
void gate_mlp(const float* __restrict__ g1w, const float* __restrict__ g1b,
              const float* __restrict__ g2w, const float* __restrict__ g2b)
{
    const int b = blockIdx.x, tid = threadIdx.x;
    __shared__ float p[NC];
    for (int c = tid; c < NC; c += 64) p[c] = g_pool[b * NC + c];
    __syncthreads();
    __shared__ float hbuf[64];
    {
        float s = g1b[tid];
        #pragma unroll 4
        for (int c = 0; c < NC; c++) s = fmaf(g1w[tid * NC + c], p[c], s);
        hbuf[tid] = fmaxf(s, 0.f);
    }
    __syncthreads();
    if (tid == 0) {
        float s = g2b[0];
        #pragma unroll
        for (int o = 0; o < 64; o++) s = fmaf(g2w[o], hbuf[o], s);
        g_gate[b] = 1.f / (1.f + __expf(-s));
    }
}

// ================= softmax in-place on fp16 S rows -> P fp16 =================
__global__ __launch_bounds__(256)
void softmax_rows()
{
    __half* row = g_p + (size_t)blockIdx.x * NPIX;
    const int tid = threadIdx.x;
    float4* r4 = reinterpret_cast<float4*>(row);
    float v[16];
    #pragma unroll
    for (int i = 0; i < 2; i++) {
        float4 q = r4[tid + (i << 8)];
        const __half2* hp = reinterpret_cast<const __half2*>(&q);
        #pragma unroll
        for (int j = 0; j < 4; j++) {
            float2 f = __half22float2(hp[j]);
            v[i * 8 + j * 2]     = f.x;
            v[i * 8 + j * 2 + 1] = f.y;
        }
    }

    float m = v[0];
    #pragma unroll
    for (int i = 1; i < 16; i++) m = fmaxf(m, v[i]);
    #pragma unroll
    for (int o = 16; o; o >>= 1) m = fmaxf(m, __shfl_xor_sync(0xffffffffu, m, o));
    __shared__ float sm[8], ss[8];
    if ((tid & 31) == 0) sm[tid >> 5] = m;
    __syncthreads();
    #pragma unroll
    for (int w = 0; w < 8; w++) m = fmaxf(m, sm[w]);

    float s = 0.f;
    #pragma unroll
    for (int i = 0; i < 16; i++) { v[i] = __expf(v[i] - m); s += v[i]; }
    #pragma unroll
    for (int o = 16; o; o >>= 1) s += __shfl_xor_sync(0xffffffffu, s, o);
    if ((tid & 31) == 0) ss[tid >> 5] = s;
    __syncthreads();
    s = 0.f;
    #pragma unroll
    for (int w = 0; w < 8; w++) s += ss[w];

    const float r = 1.f / s;
    #pragma unroll
    for (int i = 0; i < 2; i++) {
        float4 q;
        __half2* hp = reinterpret_cast<__half2*>(&q);
        #pragma unroll
        for (int j = 0; j < 4; j++)
            hp[j] = __floats2half2_rn(v[i * 8 + j * 2] * r, v[i * 8 + j * 2 + 1] * r);
        r4[tid + (i << 8)] = q;
    }
}

// ================= dwconv3x3 + BN + SiLU + gate*O^T -> fused [c][n] =================
__global__ __launch_bounds__(256)
void fuse_kernel(const float* __restrict__ xs,
                 const float* __restrict__ dww, const float* __restrict__ dwb,
                 const float* __restrict__ bng, const float* __restrict__ bnb,
                 const float* __restrict__ bnm, const float* __restrict__ bnv)
{
    const int bc = blockIdx.x;
    const int b = bc >> 8, c = bc & 255;
    const int tid = threadIdx.x;
    __shared__ float t[66 * 66];
    const float* x = xs + (size_t)bc * NPIX;
    for (int i = tid; i < 66 * 66; i += 256) {
        int h = i / 66 - 1, w = i % 66 - 1;
        t[i] = (h >= 0 && h < 64 && w >= 0 && w < 64) ? x[h * 64 + w] : 0.f;
    }
    float wt[9];
    #pragma unroll
    for (int k = 0; k < 9; k++) wt[k] = dww[c * 9 + k];
    float scale = bng[c] * rsqrtf(bnv[c] + 1e-5f);
    float shift = fmaf(dwb[c] - bnm[c], scale, bnb[c]);
    float gate = g_gate[b];
    float* fptr = g_fused + (size_t)bc * NPIX;
    const float* optr = g_o + (size_t)bc * NPIX;   // O^T [c][n] — coalesced
    __syncthreads();
    for (int i = tid; i < NPIX; i += 256) {
        int h = i >> 6, w = i & 63;
        const float* tp = &t[h * 66 + w];
        float conv = tp[0]   * wt[0] + tp[1]   * wt[1] + tp[2]   * wt[2]
                   + tp[66]  * wt[3] + tp[67]  * wt[4] + tp[68]  * wt[5]
                   + tp[132] * wt[6] + tp[133] * wt[7] + tp[134] * wt[8];
        float y = fmaf(conv, scale, shift);
        float lf = y / (1.f + __expf(-y));
        fptr[i] = fmaf(gate, optr[i], lf);
    }
}

// ================= launch =================
extern "C" void kernel_launch(void* const* d_in, const int* in_sizes, int n_in,
                              void* d_out, int out_size)
{
    const float* x_self  = (const float*)d_in[0];
    const float* x_other = (const float*)d_in[1];
    const float* q_w  = (const float*)d_in[2];
    const float* q_b  = (const float*)d_in[3];
    const float* kv_w = (const float*)d_in[4];
    const float* kv_b = (const float*)d_in[5];
    const float* g1_w = (const float*)d_in[6];
    const float* g1_b = (const float*)d_in[7];
    const float* g2_w = (const float*)d_in[8];
    const float* g2_b = (const float*)d_in[9];
    const float* dw_w = (const float*)d_in[10];
    const float* dw_b = (const float*)d_in[11];
    const float* bn_g = (const float*)d_in[12];
    const float* bn_b = (const float*)d_in[13];
    const float* bn_m = (const float*)d_in[14];
    const float* bn_v = (const float*)d_in[15];
    const float* out_w = (const float*)d_in[16];
    const float* out_b = (const float*)d_in[17];
    float* out = (float*)d_out;

    cudaFuncSetAttribute(mma_gemm<1, 2, 2>, cudaFuncAttributeMaxDynamicSharedMemorySize, SMTOT1);
    cudaFuncSetAttribute(mma_gemm<1, 1, 2>, cudaFuncAttributeMaxDynamicSharedMemorySize, SMTOT1);
    cudaFuncSetAttribute(mma_gemm<1, 0, 2>, cudaFuncAttributeMaxDynamicSharedMemorySize, SMTOT1);
    cudaFuncSetAttribute(mma_gemm<1, 0, 0>, cudaFuncAttributeMaxDynamicSharedMemorySize, SMTOT1);
    cudaFuncSetAttribute(mma_gemm<2, 1, 0>, cudaFuncAttributeMaxDynamicSharedMemorySize, SMTOT2);

    #define SYM(p, s) cudaGetSymbolAddress((void**)&p, s)
    __half *xsh, *xoh, *qth, *kth, *vh, *ph, *fth, *qwh, *kvwh, *owh, *owl;
    float *op, *fp;
    SYM(xsh, g_xs_hi); SYM(xoh, g_xo_hi);
    SYM(qth, g_qt_hi); SYM(kth, g_kt_hi); SYM(vh, g_v_hi);   SYM(ph, g_p);
    SYM(fth, g_ft_hi); SYM(qwh, g_qw_hi); SYM(kvwh, g_kvw_hi);
    SYM(owh, g_ow_hi); SYM(owl, g_ow_lo);
    SYM(op, g_o); SYM(fp, g_fused);
    #undef SYM

    const long long sX = (long long)NPIX * NC;
    const long long sS = (long long)NPIX * NPIX;

    pool_kernel<<<dim3(NC, NB), 128>>>(x_self);
    gate_mlp<<<NB, 64>>>(g1_w, g1_b, g2_w, g2_b);
    wsplit<<<4 * NC * NC / 256, 256>>>(q_w, kv_w, out_w);
    tconv_pair<<<dim3(NPIX / 32, NC / 64, 2 * NB), dim3(32, 8)>>>(
        x_self, xsh, x_other, xoh, NC, NPIX);

    // Qt[n][o] = sum_c xs[n][c] qw[o][c] + q_b[o]   (fp16 out, col bias, 1-term)
    mma_gemm<1, 2, 2><<<dim3(2, 32, NB), 256, SMTOT1>>>(
        xsh, nullptr, qwh, q_b, 1.f, nullptr, qth, NC, NC, sX, 0, sX);
    // Kt[m][o] = sum_c xo[m][c] kvw[o][c] + kv_b[o]   (1-term)
    mma_gemm<1, 2, 2><<<dim3(2, 32, NB), 256, SMTOT1>>>(
        xoh, nullptr, kvwh, kv_b, 1.f, nullptr, kth, NC, NC, sX, 0, sX);
    // V[c][n] = sum_k kvw2[c][k] xo[n][k] + kv_b[256+c]   (fp16 out, row bias, 1-term)
    mma_gemm<1, 1, 2><<<dim3(32, 2, NB), 256, SMTOT1>>>(
        kvwh + NC * NC, nullptr, xoh, kv_b + NC, 1.f,
        nullptr, vh, NC, NPIX, 0, sX, sX);
    // S[n][m] = (1/16) sum_c Qt[n][c] Kt[m][c]   (fp16 out, 1-term)
    mma_gemm<1, 0, 2><<<dim3(32, 32, NB), 256, SMTOT1>>>(
        qth, nullptr, kth, nullptr, 0.0625f, nullptr, ph, NC, NPIX, sX, sX, sS);

    softmax_rows<<<NB * NPIX, 256>>>();

    // O^T[c][n] = sum_m V[c][m] P[n][m]   (fp32 out, 1-term, M=256 N=4096)
    mma_gemm<1, 0, 0><<<dim3(32, 2, NB), 256, SMTOT1>>>(
        vh, nullptr, ph, nullptr, 1.f, op, nullptr, NPIX, NPIX, sX, sS, sX);

    fuse_kernel<<<NB * NC, 256>>>(x_self, dw_w, dw_b, bn_g, bn_b, bn_m, bn_v);
    tconv1<<<dim3(NPIX / 32, NC / 64, NB), dim3(32, 8)>>>(fp, fth, NC, NPIX);

    // out[o][n] = sum_c ow[o][c] ft[n][c] + out_b[o]   (fp32, row bias, 2-term on ow)
    mma_gemm<2, 1, 0><<<dim3(32, 2, NB), 256, SMTOT2>>>(
        owh, owl, fth, out_b, 1.f, out, nullptr, NC, NPIX, 0, sX, sX);
}

// round 11
// speedup vs baseline: 2.8303x; 1.0595x over previous
#include <cuda_runtime.h>
#include <cuda_fp16.h>
#include <cstdint>
#include <math.h>

#define NB   4
#define NC   256
#define NPIX 4096

// ================= scratch (no allocations allowed) =================
__device__ __align__(128) __half g_xs_hi[(size_t)NB*NPIX*NC];   // x_self^T [n][c]
__device__ __align__(128) __half g_xo_hi[(size_t)NB*NPIX*NC];   // x_other^T [n][c]
__device__ __align__(128) __half g_qt_hi[(size_t)NB*NPIX*NC];   // Q^T [n][c]
__device__ __align__(128) __half g_kt_hi[(size_t)NB*NPIX*NC];   // K^T [m][c]
__device__ __align__(128) __half g_v_hi [(size_t)NB*NC*NPIX];   // V [c][m]
__device__ __align__(128) __half g_p    [(size_t)NB*NPIX*NPIX]; // exp(S) [n][m] fp16 (unnormalized)
__device__ __align__(128) float  g_o    [(size_t)NB*NC*NPIX];   // O^T [c][n] fp32 (normalized)
__device__ __align__(128) float  g_fused[(size_t)NB*NC*NPIX];   // fused [c][n] fp32
__device__ __align__(128) __half g_ft_hi[(size_t)NB*NPIX*NC];   // fused^T [n][c]
__device__ __align__(128) __half g_qw_hi[NC*NC];
__device__ __align__(128) __half g_kvw_hi[2*NC*NC];
__device__ __align__(128) __half g_ow_hi[NC*NC], g_ow_lo[NC*NC];
__device__ float g_rowsum[NB*NPIX];   // per-row sums of exp(S), atomically accumulated
__device__ float g_pool[NB*NC];
__device__ float g_gate[NB];

// ================= helpers =================
__device__ __forceinline__ uint32_t smem_u32(const void* p) {
    uint32_t a;
    asm("{ .reg .u64 t; cvta.to.shared.u64 t, %1; cvt.u32.u64 %0, t; }" : "=r"(a) : "l"(p));
    return a;
}
__device__ __forceinline__ void ldm_x4(uint32_t* r, uint32_t addr) {
    asm volatile("ldmatrix.sync.aligned.m8n8.x4.shared.b16 {%0,%1,%2,%3}, [%4];"
        : "=r"(r[0]), "=r"(r[1]), "=r"(r[2]), "=r"(r[3]) : "r"(addr));
}
__device__ __forceinline__ void mma_f16(float* d, const uint32_t* a, uint32_t b0, uint32_t b1) {
    asm volatile("mma.sync.aligned.m16n8k16.row.col.f32.f16.f16.f32 "
        "{%0,%1,%2,%3}, {%4,%5,%6,%7}, {%8,%9}, {%0,%1,%2,%3};"
        : "+f"(d[0]), "+f"(d[1]), "+f"(d[2]), "+f"(d[3])
        : "r"(a[0]), "r"(a[1]), "r"(a[2]), "r"(a[3]), "r"(b0), "r"(b1));
}
#define CP_ASYNC16(saddr, gptr) \
    asm volatile("cp.async.cg.shared.global [%0], [%1], 16;" :: "r"(saddr), "l"(gptr))
#define CP_COMMIT() asm volatile("cp.async.commit_group;" ::: "memory")
#define CP_WAIT0()  asm volatile("cp.async.wait_group 0;" ::: "memory")

__device__ __forceinline__ uint32_t swz(uint32_t o) { return o ^ ((o >> 3) & 0x70); }

__device__ __forceinline__ void split2(float v, __half& h, __half& l) {
    h = __float2half(v);
    l = __float2half(v - __half2float(h));
}

// ================= mma.sync GEMM: D[m][n] = alpha*sum_k A[m][k]*B[n][k] (+bias) =================
// fp16 K-major operands. NTERMS=1: Ah*Bh. NTERMS=2: Ah*Bh + Al*Bh.
// CTA tile 128x128, warp tile 32x64, K-chunks of 64, double-buffered cp.async.
// BIAS_MODE: 0 none, 1 per-row (M), 2 per-col (N), 3 col-scale by 1/g_rowsum[n].
// OUT_MODE:  0 fp32, 2 fp16, 3 fp16 exp() + atomic row-sum into g_rowsum.
#define A_TILE  16384
#define SMTOT1  (2 * 2 * A_TILE)              // 65536
#define SMTOT2  (2 * 3 * A_TILE)              // 98304

__device__ __forceinline__ void cp_tile(uint32_t dst, const __half* src, int K, int tid) {
    #pragma unroll
    for (int r = 0; r < 4; r++) {
        int idx = tid + (r << 8);
        int row = idx >> 3, cc = idx & 7;
        CP_ASYNC16(dst + swz(row * 128 + cc * 16), src + (size_t)row * K + cc * 8);
    }
}

template<int NTERMS, int BIAS_MODE, int OUT_MODE>
__global__ __launch_bounds__(256, 2)
void mma_gemm(const __half* __restrict__ Ah, const __half* __restrict__ Al,
              const __half* __restrict__ Bh,
              const float* __restrict__ bias, float alpha,
              float* __restrict__ Cf, __half* __restrict__ Ch,
              int K, int ldc, long long sA, long long sB, long long sC)
{
    constexpr uint32_t STG = (NTERMS + 1) * A_TILE;
    extern __shared__ __align__(1024) char dsm[];
    const uint32_t sb = smem_u32(dsm);
    const int tid = threadIdx.x, wid = tid >> 5, lane = tid & 31;
    const int warp_m = wid & 3, warp_n = wid >> 2;

    const size_t m0 = (size_t)blockIdx.y << 7;
    const size_t n0 = (size_t)blockIdx.x << 7;
    const __half* pah = Ah + (long long)blockIdx.z * sA + m0 * K;
    const __half* pal = (NTERMS == 2) ? (Al + (long long)blockIdx.z * sA + m0 * K) : nullptr;
    const __half* pbh = Bh + (long long)blockIdx.z * sB + n0 * K;

    float acc[2][8][4];
    #pragma unroll
    for (int i = 0; i < 2; i++)
        #pragma unroll
        for (int j = 0; j < 8; j++)
            #pragma unroll
            for (int q = 0; q < 4; q++) acc[i][j][q] = 0.f;

    const uint32_t BH_OFF = NTERMS * A_TILE;
    const int nch = K >> 6;
    cp_tile(sb, pah, K, tid);
    if (NTERMS == 2) cp_tile(sb + A_TILE, pal, K, tid);
    cp_tile(sb + BH_OFF, pbh, K, tid);
    CP_COMMIT();

    for (int ch = 0; ch < nch; ch++) {
        CP_WAIT0();
        __syncthreads();
        if (ch + 1 < nch) {
            const size_t k0 = (size_t)(ch + 1) << 6;
            const uint32_t nb = sb + ((ch + 1) & 1) * STG;
            cp_tile(nb, pah + k0, K, tid);
            if (NTERMS == 2) cp_tile(nb + A_TILE, pal + k0, K, tid);
            cp_tile(nb + BH_OFF, pbh + k0, K, tid);
            CP_COMMIT();
        }
        const uint32_t cbAH = sb + (ch & 1) * STG;
        const uint32_t cbAL = cbAH + A_TILE;
        const uint32_t cbBH = cbAH + BH_OFF;

        #pragma unroll
        for (int ks = 0; ks < 4; ks++) {
            const uint32_t koff = ks * 32 + (lane >> 4) * 16;
            uint32_t a_hi[2][4], a_lo[2][4];
            #pragma unroll
            for (int im = 0; im < 2; im++) {
                uint32_t off = swz((warp_m * 32 + im * 16 + (lane & 15)) * 128 + koff);
                ldm_x4(a_hi[im], cbAH + off);
                if (NTERMS == 2) ldm_x4(a_lo[im], cbAL + off);
            }
            #pragma unroll
            for (int in2 = 0; in2 < 4; in2++) {
                uint32_t off = swz((warp_n * 64 + in2 * 16 + (lane & 15)) * 128 + koff);
                uint32_t bh[4];
                ldm_x4(bh, cbBH + off);
                #pragma unroll
                for (int im = 0; im < 2; im++) {
                    #pragma unroll
                    for (int s = 0; s < 2; s++) {
                        float* d = acc[im][in2 * 2 + s];
                        mma_f16(d, a_hi[im], bh[s], bh[s + 2]);
                        if (NTERMS == 2) mma_f16(d, a_lo[im], bh[s], bh[s + 2]);
                    }
                }
            }
        }
        __syncthreads();
    }

    // ---------------- epilogue ----------------
    const long long cbase = (long long)blockIdx.z * sC;
    const long long zrs = (long long)blockIdx.z * NPIX;
    #pragma unroll
    for (int im = 0; im < 2; im++) {
        const int r0 = (int)m0 + warp_m * 32 + im * 16 + (lane >> 2);
        const int r1 = r0 + 8;
        float rb0 = 0.f, rb1 = 0.f;
        if (BIAS_MODE == 1) { rb0 = bias[r0]; rb1 = bias[r1]; }
        float esum0 = 0.f, esum1 = 0.f;
        #pragma unroll
        for (int in = 0; in < 8; in++) {
            const int c = (int)n0 + warp_n * 64 + in * 8 + (lane & 3) * 2;
            float cb0 = rb0, cb1 = rb0, cb2 = rb1, cb3 = rb1;
            if (BIAS_MODE == 2) { cb0 = cb2 = bias[c]; cb1 = cb3 = bias[c + 1]; }
            float v0 = fmaf(alpha, acc[im][in][0], cb0);
            float v1 = fmaf(alpha, acc[im][in][1], cb1);
            float v2 = fmaf(alpha, acc[im][in][2], cb2);
            float v3 = fmaf(alpha, acc[im][in][3], cb3);
            if (BIAS_MODE == 3) {
                float i0 = __fdividef(1.f, g_rowsum[zrs + c]);
                float i1 = __fdividef(1.f, g_rowsum[zrs + c + 1]);
                v0 *= i0; v1 *= i1; v2 *= i0; v3 *= i1;
            }
            if (OUT_MODE == 3) {
                __half h0 = __float2half(__expf(v0));
                __half h1 = __float2half(__expf(v1));
                __half h2 = __float2half(__expf(v2));
                __half h3 = __float2half(__expf(v3));
                esum0 += __half2float(h0) + __half2float(h1);
                esum1 += __half2float(h2) + __half2float(h3);
                *reinterpret_cast<__half2*>(Ch + cbase + (size_t)r0 * ldc + c) = __halves2half2(h0, h1);
                *reinterpret_cast<__half2*>(Ch + cbase + (size_t)r1 * ldc + c) = __halves2half2(h2, h3);
            } else if (OUT_MODE == 2) {
                *reinterpret_cast<__half2*>(Ch + cbase + (size_t)r0 * ldc + c) =
                    __halves2half2(__float2half(v0), __float2half(v1));
                *reinterpret_cast<__half2*>(Ch + cbase + (size_t)r1 * ldc + c) =
                    __halves2half2(__float2half(v2), __float2half(v3));
            } else {
                *reinterpret_cast<float2*>(Cf + cbase + (size_t)r0 * ldc + c) = make_float2(v0, v1);
                *reinterpret_cast<float2*>(Cf + cbase + (size_t)r1 * ldc + c) = make_float2(v2, v3);
            }
        }
        if (OUT_MODE == 3) {
            // lanes 4j..4j+3 share rows r0/r1 (different columns) — reduce then one atomic
            esum0 += __shfl_xor_sync(0xffffffffu, esum0, 1);
            esum0 += __shfl_xor_sync(0xffffffffu, esum0, 2);
            esum1 += __shfl_xor_sync(0xffffffffu, esum1, 1);
            esum1 += __shfl_xor_sync(0xffffffffu, esum1, 2);
            if ((lane & 3) == 0) {
                atomicAdd(&g_rowsum[zrs + r0], esum0);
                atomicAdd(&g_rowsum[zrs + r1], esum1);
            }
        }
    }
}

// ================= transpose + fp16 convert (hi only) =================
__device__ __forceinline__ void tconv_body(const float* src, __half* dh, int R, int C) {
    __shared__ float t[64][33];
    const int c0 = blockIdx.x * 32, r0 = blockIdx.y * 64;
    const int tx = threadIdx.x, ty = threadIdx.y;
    #pragma unroll
    for (int i = 0; i < 8; i++)
        t[ty + 8 * i][tx] = src[(size_t)(r0 + ty + 8 * i) * C + c0 + tx];
    __syncthreads();
    #pragma unroll
    for (int i = 0; i < 4; i++) {
        const int pixl = ty + 8 * i;
        size_t o = (size_t)(c0 + pixl) * R + r0 + 2 * tx;
        *reinterpret_cast<__half2*>(dh + o) =
            __floats2half2_rn(t[2 * tx][pixl], t[2 * tx + 1][pixl]);
    }
}

__global__ void tconv_pair(const float* __restrict__ sA, __half* __restrict__ dA,
                           const float* __restrict__ sB, __half* __restrict__ dB,
                           int R, int C)
{
    const int sel = blockIdx.z & 1, b = blockIdx.z >> 1;
    const float* src = (sel ? sB : sA) + (size_t)b * R * C;
    __half* dh = (sel ? dB : dA) + (size_t)b * R * C;
    tconv_body(src, dh, R, C);
}

__global__ void tconv1(const float* __restrict__ s, __half* __restrict__ d, int R, int C)
{
    tconv_body(s + (size_t)blockIdx.z * R * C, d + (size_t)blockIdx.z * R * C, R, C);
}

// ================= weight split: qw hi, kvw hi, ow hi+lo =================
__global__ void wsplit(const float* __restrict__ qw, const float* __restrict__ kvw,
                       const float* __restrict__ ow)
{
    int i = blockIdx.x * 256 + threadIdx.x;
    if (i < NC * NC) {
        g_qw_hi[i] = __float2half(qw[i]);
    } else if (i < 3 * NC * NC) {
        int off = i - NC * NC;
        g_kvw_hi[off] = __float2half(kvw[off]);
    } else {
        int off = i - 3 * NC * NC;
        __half h, l; split2(ow[off], h, l);
        g_ow_hi[off] = h; g_ow_lo[off] = l;
    }
}

// ================= spatial mean pool + rowsum zeroing =================
__global__ __launch_bounds__(128)
void pool_kernel(const float* __restrict__ xs)
{
    const int c = blockIdx.x, b = blockIdx.y;
    const int tid = threadIdx.x, lane = tid & 31, wid = tid >> 5;
    // zero g_rowsum: 1024 blocks x 16 entries = 16384
    {
        int base = (blockIdx.y * NC + blockIdx.x) * 16;
        if (tid < 16) g_rowsum[base + tid] = 0.f;
    }
    const float4* x = reinterpret_cast<const float4*>(xs + ((size_t)b * NC + c) * NPIX);
    float s = 0.f;
    #pragma unroll
    for (int i = 0; i < 8; i++) {
        float4 v = x[tid + i * 128];
        s += (v.x + v.y) + (v.z + v.w);
    }
    #pragma unroll
    for (int o = 16; o; o >>= 1) s += __shfl_xor_sync(0xffffffffu, s, o);
    __shared__ float ws[4];
    if (!lane) ws[wid] = s;
    __syncthreads();
    if (tid == 0)
        g_pool[b * NC + c] = (ws[0] + ws[1] + ws[2] + ws[3]) * (1.0f / NPIX);
}

// ================= gate MLP (tiny) =================
__global__ __launch_bounds__(64)
void gate_mlp(const float* __restrict__ g1w, const float* __restrict__ g1b,
              const float* __restrict__ g2w, const float* __restrict__ g2b)
{
    const int b = blockIdx.x, tid = threadIdx.x;
    __shared__ float p[NC];
    for (int c = tid; c < NC; c += 64) p[c] = g_pool[b * NC + c];
    __syncthreads();
    __shared__ float hbuf[64];
    {
        float s = g1b[tid];
        #pragma unroll 4
        for (int c = 0; c < NC; c++) s = fmaf(g1w[tid * NC + c], p[c], s);
        hbuf[tid] = fmaxf(s, 0.f);
    }
    __syncthreads();
    if (tid == 0) {
        float s = g2b[0];
        #pragma unroll
        for (int o = 0; o < 64; o++) s = fmaf(g2w[o], hbuf[o], s);
        g_gate[b] = 1.f / (1.f + __expf(-s));
    }
}

// ================= dwconv3x3 + BN + SiLU + gate*O^T -> fused [c][n] =================
__global__ __launch_bounds__(256)
void fuse_kernel(const float* __restrict__ xs,
                 const float* __restrict__ dww, const float* __restrict__ dwb,
                 const float* __restrict__ bng, const float* __restrict__ bnb,
                 const float* __restrict__ bnm, const float* __restrict__ bnv)
{
    const int bc = blockIdx.x;
    const int b = bc >> 8, c = bc & 255;
    const int tid = threadIdx.x;
    __shared__ float t[66 * 66];
    const float* x = xs + (size_t)bc * NPIX;
    for (int i = tid; i < 66 * 66; i += 256) {
        int h = i / 66 - 1, w = i % 66 - 1;
        t[i] = (h >= 0 && h < 64 && w >= 0 && w < 64) ? x[h * 64 + w] : 0.f;
    }
    float wt[9];
    #pragma unroll
    for (int k = 0; k < 9; k++) wt[k] = dww[c * 9 + k];
    float scale = bng[c] * rsqrtf(bnv[c] + 1e-5f);
    float shift = fmaf(dwb[c] - bnm[c], scale, bnb[c]);
    float gate = g_gate[b];
    float* fptr = g_fused + (size_t)bc * NPIX;
    const float* optr = g_o + (size_t)bc * NPIX;   // O^T [c][n] — coalesced
    __syncthreads();
    for (int i = tid; i < NPIX; i += 256) {
        int h = i >> 6, w = i & 63;
        const float* tp = &t[h * 66 + w];
        float conv = tp[0]   * wt[0] + tp[1]   * wt[1] + tp[2]   * wt[2]
                   + tp[66]  * wt[3] + tp[67]  * wt[4] + tp[68]  * wt[5]
                   + tp[132] * wt[6] + tp[133] * wt[7] + tp[134] * wt[8];
        float y = fmaf(conv, scale, shift);
        float lf = y / (1.f + __expf(-y));
        fptr[i] = fmaf(gate, optr[i], lf);
    }
}

// ================= launch =================
extern "C" void kernel_launch(void* const* d_in, const int* in_sizes, int n_in,
                              void* d_out, int out_size)
{
    const float* x_self  = (const float*)d_in[0];
    const float* x_other = (const float*)d_in[1];
    const float* q_w  = (const float*)d_in[2];
    const float* q_b  = (const float*)d_in[3];
    const float* kv_w = (const float*)d_in[4];
    const float* kv_b = (const float*)d_in[5];
    const float* g1_w = (const float*)d_in[6];
    const float* g1_b = (const float*)d_in[7];
    const float* g2_w = (const float*)d_in[8];
    const float* g2_b = (const float*)d_in[9];
    const float* dw_w = (const float*)d_in[10];
    const float* dw_b = (const float*)d_in[11];
    const float* bn_g = (const float*)d_in[12];
    const float* bn_b = (const float*)d_in[13];
    const float* bn_m = (const float*)d_in[14];
    const float* bn_v = (const float*)d_in[15];
    const float* out_w = (const float*)d_in[16];
    const float* out_b = (const float*)d_in[17];
    float* out = (float*)d_out;

    cudaFuncSetAttribute(mma_gemm<1, 2, 2>, cudaFuncAttributeMaxDynamicSharedMemorySize, SMTOT1);
    cudaFuncSetAttribute(mma_gemm<1, 1, 2>, cudaFuncAttributeMaxDynamicSharedMemorySize, SMTOT1);
    cudaFuncSetAttribute(mma_gemm<1, 0, 3>, cudaFuncAttributeMaxDynamicSharedMemorySize, SMTOT1);
    cudaFuncSetAttribute(mma_gemm<1, 3, 0>, cudaFuncAttributeMaxDynamicSharedMemorySize, SMTOT1);
    cudaFuncSetAttribute(mma_gemm<2, 1, 0>, cudaFuncAttributeMaxDynamicSharedMemorySize, SMTOT2);

    #define SYM(p, s) cudaGetSymbolAddress((void**)&p, s)
    __half *xsh, *xoh, *qth, *kth, *vh, *ph, *fth, *qwh, *kvwh, *owh, *owl;
    float *op, *fp;
    SYM(xsh, g_xs_hi); SYM(xoh, g_xo_hi);
    SYM(qth, g_qt_hi); SYM(kth, g_kt_hi); SYM(vh, g_v_hi);   SYM(ph, g_p);
    SYM(fth, g_ft_hi); SYM(qwh, g_qw_hi); SYM(kvwh, g_kvw_hi);
    SYM(owh, g_ow_hi); SYM(owl, g_ow_lo);
    SYM(op, g_o); SYM(fp, g_fused);
    #undef SYM

    const long long sX = (long long)NPIX * NC;
    const long long sS = (long long)NPIX * NPIX;

    pool_kernel<<<dim3(NC, NB), 128>>>(x_self);          // also zeroes g_rowsum
    gate_mlp<<<NB, 64>>>(g1_w, g1_b, g2_w, g2_b);
    wsplit<<<4 * NC * NC / 256, 256>>>(q_w, kv_w, out_w);
    tconv_pair<<<dim3(NPIX / 32, NC / 64, 2 * NB), dim3(32, 8)>>>(
        x_self, xsh, x_other, xoh, NC, NPIX);

    // Qt[n][o] = sum_c xs[n][c] qw[o][c] + q_b[o]   (fp16 out, col bias, 1-term)
    mma_gemm<1, 2, 2><<<dim3(2, 32, NB), 256, SMTOT1>>>(
        xsh, nullptr, qwh, q_b, 1.f, nullptr, qth, NC, NC, sX, 0, sX);
    // Kt[m][o] = sum_c xo[m][c] kvw[o][c] + kv_b[o]   (1-term)
    mma_gemm<1, 2, 2><<<dim3(2, 32, NB), 256, SMTOT1>>>(
        xoh, nullptr, kvwh, kv_b, 1.f, nullptr, kth, NC, NC, sX, 0, sX);
    // V[c][n] = sum_k kvw2[c][k] xo[n][k] + kv_b[256+c]   (fp16 out, row bias, 1-term)
    mma_gemm<1, 1, 2><<<dim3(32, 2, NB), 256, SMTOT1>>>(
        kvwh + NC * NC, nullptr, xoh, kv_b + NC, 1.f,
        nullptr, vh, NC, NPIX, 0, sX, sX);
    // P[n][m] = exp(S[n][m]) fp16 + row sums  (S = (1/16) Qt·Kt^T, 1-term, no softmax kernel)
    mma_gemm<1, 0, 3><<<dim3(32, 32, NB), 256, SMTOT1>>>(
        qth, nullptr, kth, nullptr, 0.0625f, nullptr, ph, NC, NPIX, sX, sX, sS);

    // O^T[c][n] = (sum_m V[c][m] P[n][m]) / rowsum[n]   (fp32 out, col-scale epilogue)
    mma_gemm<1, 3, 0><<<dim3(32, 2, NB), 256, SMTOT1>>>(
        vh, nullptr, ph, nullptr, 1.f, op, nullptr, NPIX, NPIX, sX, sS, sX);

    fuse_kernel<<<NB * NC, 256>>>(x_self, dw_w, dw_b, bn_g, bn_b, bn_m, bn_v);
    tconv1<<<dim3(NPIX / 32, NC / 64, NB), dim3(32, 8)>>>(fp, fth, NC, NPIX);

    // out[o][n] = sum_c ow[o][c] ft[n][c] + out_b[o]   (fp32, row bias, 2-term on ow)
    mma_gemm<2, 1, 0><<<dim3(32, 2, NB), 256, SMTOT2>>>(
        owh, owl, fth, out_b, 1.f, out, nullptr, NC, NPIX, 0, sX, sX);
}

// round 12
// speedup vs baseline: 2.9168x; 1.0306x over previous
#include <cuda_runtime.h>
#include <cuda_fp16.h>
#include <cstdint>
#include <math.h>

#define NB   4
#define NC   256
#define NPIX 4096

// ================= scratch (no allocations allowed) =================
__device__ __align__(128) __half g_xs_hi[(size_t)NB*NPIX*NC];   // x_self^T [n][c]
__device__ __align__(128) __half g_xo_hi[(size_t)NB*NPIX*NC];   // x_other^T [n][c]
__device__ __align__(128) __half g_qt_hi[(size_t)NB*NPIX*NC];   // Q^T [n][c]
__device__ __align__(128) __half g_kt_hi[(size_t)NB*NPIX*NC];   // K^T [m][c]
__device__ __align__(128) __half g_v_hi [(size_t)NB*NC*NPIX];   // V [c][m]
__device__ __align__(128) __half g_p    [(size_t)NB*NPIX*NPIX]; // exp(S) [n][m] fp16
__device__ __align__(128) __half g_oh   [(size_t)NB*NC*NPIX];   // O^T [c][n] fp16 (normalized)
__device__ __align__(128) __half g_fusedh[(size_t)NB*NC*NPIX];  // fused [c][n] fp16
__device__ __align__(128) __half g_ft_hi[(size_t)NB*NPIX*NC];   // fused^T [n][c]
__device__ __align__(128) __half g_qw_hi[NC*NC];
__device__ __align__(128) __half g_kvw_hi[2*NC*NC];
__device__ __align__(128) __half g_ow_hi[NC*NC];
__device__ float g_rowsum[NB*NPIX];   // per-row sums of exp(S)
__device__ float g_pool[NB*NC];       // per-channel sums of x_self
__device__ float g_gate[NB];

// ================= helpers =================
__device__ __forceinline__ uint32_t smem_u32(const void* p) {
    uint32_t a;
    asm("{ .reg .u64 t; cvta.to.shared.u64 t, %1; cvt.u32.u64 %0, t; }" : "=r"(a) : "l"(p));
    return a;
}
__device__ __forceinline__ void ldm_x4(uint32_t* r, uint32_t addr) {
    asm volatile("ldmatrix.sync.aligned.m8n8.x4.shared.b16 {%0,%1,%2,%3}, [%4];"
        : "=r"(r[0]), "=r"(r[1]), "=r"(r[2]), "=r"(r[3]) : "r"(addr));
}
__device__ __forceinline__ void mma_f16(float* d, const uint32_t* a, uint32_t b0, uint32_t b1) {
    asm volatile("mma.sync.aligned.m16n8k16.row.col.f32.f16.f16.f32 "
        "{%0,%1,%2,%3}, {%4,%5,%6,%7}, {%8,%9}, {%0,%1,%2,%3};"
        : "+f"(d[0]), "+f"(d[1]), "+f"(d[2]), "+f"(d[3])
        : "r"(a[0]), "r"(a[1]), "r"(a[2]), "r"(a[3]), "r"(b0), "r"(b1));
}
#define CP_ASYNC16(saddr, gptr) \
    asm volatile("cp.async.cg.shared.global [%0], [%1], 16;" :: "r"(saddr), "l"(gptr))
#define CP_COMMIT() asm volatile("cp.async.commit_group;" ::: "memory")
#define CP_WAIT0()  asm volatile("cp.async.wait_group 0;" ::: "memory")

__device__ __forceinline__ uint32_t swz(uint32_t o) { return o ^ ((o >> 3) & 0x70); }

// ================= mma.sync GEMM: D[m][n] = alpha*sum_k A[m][k]*B[n][k] (+bias) =================
// fp16 K-major operands. NTERMS=1: Ah*Bh. NTERMS=2: Ah*Bh + Al*Bh.
// BIAS_MODE: 0 none, 1 per-row (M), 2 per-col (N), 3 col-scale by 1/g_rowsum[n].
// OUT_MODE:  0 fp32, 2 fp16, 3 fp16 exp() + atomic row-sum into g_rowsum.
#define A_TILE  16384
#define SMTOT1  (2 * 2 * A_TILE)              // 65536
#define SMTOT2  (2 * 3 * A_TILE)              // 98304

__device__ __forceinline__ void cp_tile(uint32_t dst, const __half* src, int K, int tid) {
    #pragma unroll
    for (int r = 0; r < 4; r++) {
        int idx = tid + (r << 8);
        int row = idx >> 3, cc = idx & 7;
        CP_ASYNC16(dst + swz(row * 128 + cc * 16), src + (size_t)row * K + cc * 8);
    }
}

template<int NTERMS, int BIAS_MODE, int OUT_MODE>
__global__ __launch_bounds__(256, 2)
void mma_gemm(const __half* __restrict__ Ah, const __half* __restrict__ Al,
              const __half* __restrict__ Bh,
              const float* __restrict__ bias, float alpha,
              float* __restrict__ Cf, __half* __restrict__ Ch,
              int K, int ldc, long long sA, long long sB, long long sC)
{
    constexpr uint32_t STG = (NTERMS + 1) * A_TILE;
    extern __shared__ __align__(1024) char dsm[];
    const uint32_t sb = smem_u32(dsm);
    const int tid = threadIdx.x, wid = tid >> 5, lane = tid & 31;
    const int warp_m = wid & 3, warp_n = wid >> 2;

    const size_t m0 = (size_t)blockIdx.y << 7;
    const size_t n0 = (size_t)blockIdx.x << 7;
    const __half* pah = Ah + (long long)blockIdx.z * sA + m0 * K;
    const __half* pal = (NTERMS == 2) ? (Al + (long long)blockIdx.z * sA + m0 * K) : nullptr;
    const __half* pbh = Bh + (long long)blockIdx.z * sB + n0 * K;

    float acc[2][8][4];
    #pragma unroll
    for (int i = 0; i < 2; i++)
        #pragma unroll
        for (int j = 0; j < 8; j++)
            #pragma unroll
            for (int q = 0; q < 4; q++) acc[i][j][q] = 0.f;

    const uint32_t BH_OFF = NTERMS * A_TILE;
    const int nch = K >> 6;
    cp_tile(sb, pah, K, tid);
    if (NTERMS == 2) cp_tile(sb + A_TILE, pal, K, tid);
    cp_tile(sb + BH_OFF, pbh, K, tid);
    CP_COMMIT();

    for (int ch = 0; ch < nch; ch++) {
        CP_WAIT0();
        __syncthreads();
        if (ch + 1 < nch) {
            const size_t k0 = (size_t)(ch + 1) << 6;
            const uint32_t nb = sb + ((ch + 1) & 1) * STG;
            cp_tile(nb, pah + k0, K, tid);
            if (NTERMS == 2) cp_tile(nb + A_TILE, pal + k0, K, tid);
            cp_tile(nb + BH_OFF, pbh + k0, K, tid);
            CP_COMMIT();
        }
        const uint32_t cbAH = sb + (ch & 1) * STG;
        const uint32_t cbAL = cbAH + A_TILE;
        const uint32_t cbBH = cbAH + BH_OFF;

        #pragma unroll
        for (int ks = 0; ks < 4; ks++) {
            const uint32_t koff = ks * 32 + (lane >> 4) * 16;
            uint32_t a_hi[2][4], a_lo[2][4];
            #pragma unroll
            for (int im = 0; im < 2; im++) {
                uint32_t off = swz((warp_m * 32 + im * 16 + (lane & 15)) * 128 + koff);
                ldm_x4(a_hi[im], cbAH + off);
                if (NTERMS == 2) ldm_x4(a_lo[im], cbAL + off);
            }
            #pragma unroll
            for (int in2 = 0; in2 < 4; in2++) {
                uint32_t off = swz((warp_n * 64 + in2 * 16 + (lane & 15)) * 128 + koff);
                uint32_t bh[4];
                ldm_x4(bh, cbBH + off);
                #pragma unroll
                for (int im = 0; im < 2; im++) {
                    #pragma unroll
                    for (int s = 0; s < 2; s++) {
                        float* d = acc[im][in2 * 2 + s];
                        mma_f16(d, a_hi[im], bh[s], bh[s + 2]);
                        if (NTERMS == 2) mma_f16(d, a_lo[im], bh[s], bh[s + 2]);
                    }
                }
            }
        }
        __syncthreads();
    }

    // ---------------- epilogue ----------------
    const long long cbase = (long long)blockIdx.z * sC;
    const long long zrs = (long long)blockIdx.z * NPIX;
    #pragma unroll
    for (int im = 0; im < 2; im++) {
        const int r0 = (int)m0 + warp_m * 32 + im * 16 + (lane >> 2);
        const int r1 = r0 + 8;
        float rb0 = 0.f, rb1 = 0.f;
        if (BIAS_MODE == 1) { rb0 = bias[r0]; rb1 = bias[r1]; }
        float esum0 = 0.f, esum1 = 0.f;
        #pragma unroll
        for (int in = 0; in < 8; in++) {
            const int c = (int)n0 + warp_n * 64 + in * 8 + (lane & 3) * 2;
            float cb0 = rb0, cb1 = rb0, cb2 = rb1, cb3 = rb1;
            if (BIAS_MODE == 2) { cb0 = cb2 = bias[c]; cb1 = cb3 = bias[c + 1]; }
            float v0 = fmaf(alpha, acc[im][in][0], cb0);
            float v1 = fmaf(alpha, acc[im][in][1], cb1);
            float v2 = fmaf(alpha, acc[im][in][2], cb2);
            float v3 = fmaf(alpha, acc[im][in][3], cb3);
            if (BIAS_MODE == 3) {
                float i0 = __fdividef(1.f, g_rowsum[zrs + c]);
                float i1 = __fdividef(1.f, g_rowsum[zrs + c + 1]);
                v0 *= i0; v1 *= i1; v2 *= i0; v3 *= i1;
            }
            if (OUT_MODE == 3) {
                __half h0 = __float2half(__expf(v0));
                __half h1 = __float2half(__expf(v1));
                __half h2 = __float2half(__expf(v2));
                __half h3 = __float2half(__expf(v3));
                esum0 += __half2float(h0) + __half2float(h1);
                esum1 += __half2float(h2) + __half2float(h3);
                *reinterpret_cast<__half2*>(Ch + cbase + (size_t)r0 * ldc + c) = __halves2half2(h0, h1);
                *reinterpret_cast<__half2*>(Ch + cbase + (size_t)r1 * ldc + c) = __halves2half2(h2, h3);
            } else if (OUT_MODE == 2) {
                *reinterpret_cast<__half2*>(Ch + cbase + (size_t)r0 * ldc + c) =
                    __halves2half2(__float2half(v0), __float2half(v1));
                *reinterpret_cast<__half2*>(Ch + cbase + (size_t)r1 * ldc + c) =
                    __halves2half2(__float2half(v2), __float2half(v3));
            } else {
                *reinterpret_cast<float2*>(Cf + cbase + (size_t)r0 * ldc + c) = make_float2(v0, v1);
                *reinterpret_cast<float2*>(Cf + cbase + (size_t)r1 * ldc + c) = make_float2(v2, v3);
            }
        }
        if (OUT_MODE == 3) {
            esum0 += __shfl_xor_sync(0xffffffffu, esum0, 1);
            esum0 += __shfl_xor_sync(0xffffffffu, esum0, 2);
            esum1 += __shfl_xor_sync(0xffffffffu, esum1, 1);
            esum1 += __shfl_xor_sync(0xffffffffu, esum1, 2);
            if ((lane & 3) == 0) {
                atomicAdd(&g_rowsum[zrs + r0], esum0);
                atomicAdd(&g_rowsum[zrs + r1], esum1);
            }
        }
    }
}

// ================= transpose + fp16 convert (hi only), optional channel-pool =================
// Tile: 64 src-rows (channels) x 32 src-cols (pixels); half2 stores along channel dim.
template<typename T>
__device__ __forceinline__ void tconv_body(const T* src, __half* dh, int R, int C,
                                           float* pool_or_null) {
    __shared__ float t[64][33];
    __shared__ float ps[64];
    const int c0 = blockIdx.x * 32, r0 = blockIdx.y * 64;
    const int tx = threadIdx.x, ty = threadIdx.y;
    const int tid = ty * 32 + tx;
    if (pool_or_null && tid < 64) ps[tid] = 0.f;
    #pragma unroll
    for (int i = 0; i < 8; i++)
        t[ty + 8 * i][tx] = (float)src[(size_t)(r0 + ty + 8 * i) * C + c0 + tx];
    __syncthreads();
    float s0 = 0.f, s1 = 0.f;
    #pragma unroll
    for (int i = 0; i < 4; i++) {
        const int pixl = ty + 8 * i;
        float v0 = t[2 * tx][pixl], v1 = t[2 * tx + 1][pixl];
        size_t o = (size_t)(c0 + pixl) * R + r0 + 2 * tx;
        *reinterpret_cast<__half2*>(dh + o) = __floats2half2_rn(v0, v1);
        s0 += v0; s1 += v1;
    }
    if (pool_or_null) {
        __syncthreads();
        atomicAdd(&ps[2 * tx], s0);
        atomicAdd(&ps[2 * tx + 1], s1);
        __syncthreads();
        if (tid < 64) atomicAdd(&pool_or_null[r0 + tid], ps[tid]);
    }
}

// paired: z = b*2 + sel  (xs pooled / xo not)
__global__ void tconv_pair(const float* __restrict__ sA, __half* __restrict__ dA,
                           const float* __restrict__ sB, __half* __restrict__ dB,
                           int R, int C)
{
    const int sel = blockIdx.z & 1, b = blockIdx.z >> 1;
    const float* src = (sel ? sB : sA) + (size_t)b * R * C;
    __half* dh = (sel ? dB : dA) + (size_t)b * R * C;
    tconv_body<float>(src, dh, R, C, sel ? nullptr : (g_pool + b * NC));
}

__global__ void tconv1h(const __half* __restrict__ s, __half* __restrict__ d, int R, int C)
{
    tconv_body<__half>(s + (size_t)blockIdx.z * R * C, d + (size_t)blockIdx.z * R * C,
                       R, C, nullptr);
}

// ================= weight convert + scratch zeroing =================
__global__ void wsplit(const float* __restrict__ qw, const float* __restrict__ kvw,
                       const float* __restrict__ ow)
{
    int i = blockIdx.x * 256 + threadIdx.x;   // 0 .. 262143
    if (i < NB * NPIX) g_rowsum[i] = 0.f;
    if (i < NB * NC)   g_pool[i]   = 0.f;
    if (i < NC * NC) {
        g_qw_hi[i] = __float2half(qw[i]);
        g_ow_hi[i] = __float2half(ow[i]);
    }
    if (i < 2 * NC * NC) g_kvw_hi[i] = __float2half(kvw[i]);
}

// ================= gate MLP (tiny; consumes pooled sums) =================
__global__ __launch_bounds__(64)
void gate_mlp(const float* __restrict__ g1w, const float* __restrict__ g1b,
              const float* __restrict__ g2w, const float* __restrict__ g2b)
{
    const int b = blockIdx.x, tid = threadIdx.x;
    __shared__ float p[NC];
    for (int c = tid; c < NC; c += 64) p[c] = g_pool[b * NC + c] * (1.0f / NPIX);
    __syncthreads();
    __shared__ float hbuf[64];
    {
        float s = g1b[tid];
        #pragma unroll 4
        for (int c = 0; c < NC; c++) s = fmaf(g1w[tid * NC + c], p[c], s);
        hbuf[tid] = fmaxf(s, 0.f);
    }
    __syncthreads();
    if (tid == 0) {
        float s = g2b[0];
        #pragma unroll
        for (int o = 0; o < 64; o++) s = fmaf(g2w[o], hbuf[o], s);
        g_gate[b] = 1.f / (1.f + __expf(-s));
    }
}

// ================= dwconv3x3 + BN + SiLU + gate*O^T -> fused fp16 [c][n] =================
__global__ __launch_bounds__(256)
void fuse_kernel(const float* __restrict__ xs,
                 const float* __restrict__ dww, const float* __restrict__ dwb,
                 const float* __restrict__ bng, const float* __restrict__ bnb,
                 const float* __restrict__ bnm, const float* __restrict__ bnv)
{
    const int bc = blockIdx.x;
    const int b = bc >> 8, c = bc & 255;
    const int tid = threadIdx.x;
    __shared__ float t[66 * 66];
    const float* x = xs + (size_t)bc * NPIX;
    for (int i = tid; i < 66 * 66; i += 256) {
        int h = i / 66 - 1, w = i % 66 - 1;
        t[i] = (h >= 0 && h < 64 && w >= 0 && w < 64) ? x[h * 64 + w] : 0.f;
    }
    float wt[9];
    #pragma unroll
    for (int k = 0; k < 9; k++) wt[k] = dww[c * 9 + k];
    float scale = bng[c] * rsqrtf(bnv[c] + 1e-5f);
    float shift = fmaf(dwb[c] - bnm[c], scale, bnb[c]);
    float gate = g_gate[b];
    __half2* fptr2 = reinterpret_cast<__half2*>(g_fusedh + (size_t)bc * NPIX);
    const __half2* optr2 = reinterpret_cast<const __half2*>(g_oh + (size_t)bc * NPIX);
    __syncthreads();
    for (int i = tid; i < NPIX / 2; i += 256) {
        int i2 = 2 * i;
        int h = i2 >> 6, w = i2 & 63;
        const float* tp = &t[h * 66 + w];
        float conv0 = tp[0]   * wt[0] + tp[1]   * wt[1] + tp[2]   * wt[2]
                    + tp[66]  * wt[3] + tp[67]  * wt[4] + tp[68]  * wt[5]
                    + tp[132] * wt[6] + tp[133] * wt[7] + tp[134] * wt[8];
        float conv1 = tp[1]   * wt[0] + tp[2]   * wt[1] + tp[3]   * wt[2]
                    + tp[67]  * wt[3] + tp[68]  * wt[4] + tp[69]  * wt[5]
                    + tp[133] * wt[6] + tp[134] * wt[7] + tp[135] * wt[8];
        float y0 = fmaf(conv0, scale, shift);
        float y1 = fmaf(conv1, scale, shift);
        float lf0 = y0 / (1.f + __expf(-y0));
        float lf1 = y1 / (1.f + __expf(-y1));
        float2 ov = __half22float2(optr2[i]);
        fptr2[i] = __floats2half2_rn(fmaf(gate, ov.x, lf0), fmaf(gate, ov.y, lf1));
    }
}

// ================= launch =================
extern "C" void kernel_launch(void* const* d_in, const int* in_sizes, int n_in,
                              void* d_out, int out_size)
{
    const float* x_self  = (const float*)d_in[0];
    const float* x_other = (const float*)d_in[1];
    const float* q_w  = (const float*)d_in[2];
    const float* q_b  = (const float*)d_in[3];
    const float* kv_w = (const float*)d_in[4];
    const float* kv_b = (const float*)d_in[5];
    const float* g1_w = (const float*)d_in[6];
    const float* g1_b = (const float*)d_in[7];
    const float* g2_w = (const float*)d_in[8];
    const float* g2_b = (const float*)d_in[9];
    const float* dw_w = (const float*)d_in[10];
    const float* dw_b = (const float*)d_in[11];
    const float* bn_g = (const float*)d_in[12];
    const float* bn_b = (const float*)d_in[13];
    const float* bn_m = (const float*)d_in[14];
    const float* bn_v = (const float*)d_in[15];
    const float* out_w = (const float*)d_in[16];
    const float* out_b = (const float*)d_in[17];
    float* out = (float*)d_out;

    cudaFuncSetAttribute(mma_gemm<1, 2, 2>, cudaFuncAttributeMaxDynamicSharedMemorySize, SMTOT1);
    cudaFuncSetAttribute(mma_gemm<1, 1, 2>, cudaFuncAttributeMaxDynamicSharedMemorySize, SMTOT1);
    cudaFuncSetAttribute(mma_gemm<1, 0, 3>, cudaFuncAttributeMaxDynamicSharedMemorySize, SMTOT1);
    cudaFuncSetAttribute(mma_gemm<1, 3, 2>, cudaFuncAttributeMaxDynamicSharedMemorySize, SMTOT1);
    cudaFuncSetAttribute(mma_gemm<1, 1, 0>, cudaFuncAttributeMaxDynamicSharedMemorySize, SMTOT1);

    #define SYM(p, s) cudaGetSymbolAddress((void**)&p, s)
    __half *xsh, *xoh, *qth, *kth, *vh, *ph, *oph, *fph, *fth, *qwh, *kvwh, *owh;
    SYM(xsh, g_xs_hi); SYM(xoh, g_xo_hi);
    SYM(qth, g_qt_hi); SYM(kth, g_kt_hi); SYM(vh, g_v_hi);   SYM(ph, g_p);
    SYM(oph, g_oh);    SYM(fph, g_fusedh); SYM(fth, g_ft_hi);
    SYM(qwh, g_qw_hi); SYM(kvwh, g_kvw_hi); SYM(owh, g_ow_hi);
    #undef SYM

    const long long sX = (long long)NPIX * NC;
    const long long sS = (long long)NPIX * NPIX;

    wsplit<<<2 * NC * NC / 256, 256>>>(q_w, kv_w, out_w);   // also zeroes pool/rowsum
    tconv_pair<<<dim3(NPIX / 32, NC / 64, 2 * NB), dim3(32, 8)>>>(
        x_self, xsh, x_other, xoh, NC, NPIX);               // also pools x_self
    gate_mlp<<<NB, 64>>>(g1_w, g1_b, g2_w, g2_b);

    // Qt[n][o] = sum_c xs[n][c] qw[o][c] + q_b[o]   (fp16 out, col bias)
    mma_gemm<1, 2, 2><<<dim3(2, 32, NB), 256, SMTOT1>>>(
        xsh, nullptr, qwh, q_b, 1.f, nullptr, qth, NC, NC, sX, 0, sX);
    // Kt[m][o] = sum_c xo[m][c] kvw[o][c] + kv_b[o]
    mma_gemm<1, 2, 2><<<dim3(2, 32, NB), 256, SMTOT1>>>(
        xoh, nullptr, kvwh, kv_b, 1.f, nullptr, kth, NC, NC, sX, 0, sX);
    // V[c][n] = sum_k kvw2[c][k] xo[n][k] + kv_b[256+c]   (fp16 out, row bias)
    mma_gemm<1, 1, 2><<<dim3(32, 2, NB), 256, SMTOT1>>>(
        kvwh + NC * NC, nullptr, xoh, kv_b + NC, 1.f,
        nullptr, vh, NC, NPIX, 0, sX, sX);
    // P[n][m] = exp((1/16) Qt·Kt^T) fp16 + row sums
    mma_gemm<1, 0, 3><<<dim3(32, 32, NB), 256, SMTOT1>>>(
        qth, nullptr, kth, nullptr, 0.0625f, nullptr, ph, NC, NPIX, sX, sX, sS);

    // O^T[c][n] = (sum_m V[c][m] P[n][m]) / rowsum[n]   (fp16 out)
    mma_gemm<1, 3, 2><<<dim3(32, 2, NB), 256, SMTOT1>>>(
        vh, nullptr, ph, nullptr, 1.f, nullptr, oph, NPIX, NPIX, sX, sS, sX);

    fuse_kernel<<<NB * NC, 256>>>(x_self, dw_w, dw_b, bn_g, bn_b, bn_m, bn_v);
    tconv1h<<<dim3(NPIX / 32, NC / 64, NB), dim3(32, 8)>>>(fph, fth, NC, NPIX);

    // out[o][n] = sum_c ow[o][c] ft[n][c] + out_b[o]   (fp32, row bias, 1-term)
    mma_gemm<1, 1, 0><<<dim3(32, 2, NB), 256, SMTOT1>>>(
        owh, nullptr, fth, out_b, 1.f, out, nullptr, NC, NPIX, 0, sX, sX);
}

// round 13
// speedup vs baseline: 2.9453x; 1.0098x over previous
#include <cuda_runtime.h>
#include <cuda_fp16.h>
#include <cstdint>
#include <math.h>

#define NB   4
#define NC   256
#define NPIX 4096

// ================= scratch (no allocations allowed) =================
__device__ __align__(128) __half g_xs_hi[(size_t)NB*NPIX*NC];   // x_self^T [n][c]
__device__ __align__(128) __half g_xo_hi[(size_t)NB*NPIX*NC];   // x_other^T [n][c]
__device__ __align__(128) __half g_qt_hi[(size_t)NB*NPIX*NC];   // Q^T [n][c]
__device__ __align__(128) __half g_kt_hi[(size_t)NB*NPIX*NC];   // K^T [m][c]
__device__ __align__(128) __half g_v_hi [(size_t)NB*NC*NPIX];   // V [c][m]
__device__ __align__(128) __half g_p    [(size_t)NB*NPIX*NPIX]; // exp(S) [n][m] fp16
__device__ __align__(128) __half g_oh   [(size_t)NB*NC*NPIX];   // O^T [c][n] fp16 (normalized)
__device__ __align__(128) __half g_fusedh[(size_t)NB*NC*NPIX];  // fused [c][n] fp16
__device__ __align__(128) __half g_ft_hi[(size_t)NB*NPIX*NC];   // fused^T [n][c]
__device__ __align__(128) __half g_qw_hi[NC*NC];
__device__ __align__(128) __half g_kvw_hi[2*NC*NC];
__device__ __align__(128) __half g_ow_hi[NC*NC];
__device__ float g_rowsum[NB*NPIX];   // per-row sums of exp(S)
__device__ float g_pool[NB*NC];       // per-channel sums of x_self
__device__ float g_gate[NB];

// ================= helpers =================
__device__ __forceinline__ uint32_t smem_u32(const void* p) {
    uint32_t a;
    asm("{ .reg .u64 t; cvta.to.shared.u64 t, %1; cvt.u32.u64 %0, t; }" : "=r"(a) : "l"(p));
    return a;
}
__device__ __forceinline__ void ldm_x4(uint32_t* r, uint32_t addr) {
    asm volatile("ldmatrix.sync.aligned.m8n8.x4.shared.b16 {%0,%1,%2,%3}, [%4];"
        : "=r"(r[0]), "=r"(r[1]), "=r"(r[2]), "=r"(r[3]) : "r"(addr));
}
__device__ __forceinline__ void mma_f16(float* d, const uint32_t* a, uint32_t b0, uint32_t b1) {
    asm volatile("mma.sync.aligned.m16n8k16.row.col.f32.f16.f16.f32 "
        "{%0,%1,%2,%3}, {%4,%5,%6,%7}, {%8,%9}, {%0,%1,%2,%3};"
        : "+f"(d[0]), "+f"(d[1]), "+f"(d[2]), "+f"(d[3])
        : "r"(a[0]), "r"(a[1]), "r"(a[2]), "r"(a[3]), "r"(b0), "r"(b1));
}
#define CP_ASYNC16(saddr, gptr) \
    asm volatile("cp.async.cg.shared.global [%0], [%1], 16;" :: "r"(saddr), "l"(gptr))
#define CP_COMMIT() asm volatile("cp.async.commit_group;" ::: "memory")
#define CP_WAIT0()  asm volatile("cp.async.wait_group 0;" ::: "memory")

__device__ __forceinline__ uint32_t swz(uint32_t o) { return o ^ ((o >> 3) & 0x70); }

#define A_TILE  16384
#define SMTOT1  (2 * 2 * A_TILE)              // 65536

__device__ __forceinline__ void cp_tile(uint32_t dst, const __half* src, int K, int tid) {
    #pragma unroll
    for (int r = 0; r < 4; r++) {
        int idx = tid + (r << 8);
        int row = idx >> 3, cc = idx & 7;
        CP_ASYNC16(dst + swz(row * 128 + cc * 16), src + (size_t)row * K + cc * 8);
    }
}

// ================= generic 1-term GEMM (S / O / out) =================
// D[m][n] = alpha*sum_k A[m][k]*B[n][k] (+bias)
// BIAS_MODE: 0 none, 1 per-row (M), 3 col-scale by 1/g_rowsum[n].
// OUT_MODE:  0 fp32, 2 fp16, 3 fp16 exp() + atomic row-sum into g_rowsum.
template<int BIAS_MODE, int OUT_MODE>
__global__ __launch_bounds__(256, 2)
void mma_gemm(const __half* __restrict__ Ah, const __half* __restrict__ Bh,
              const float* __restrict__ bias, float alpha,
              float* __restrict__ Cf, __half* __restrict__ Ch,
              int K, int ldc, long long sA, long long sB, long long sC)
{
    constexpr uint32_t STG = 2 * A_TILE;
    extern __shared__ __align__(1024) char dsm[];
    const uint32_t sb = smem_u32(dsm);
    const int tid = threadIdx.x, wid = tid >> 5, lane = tid & 31;
    const int warp_m = wid & 3, warp_n = wid >> 2;

    const size_t m0 = (size_t)blockIdx.y << 7;
    const size_t n0 = (size_t)blockIdx.x << 7;
    const __half* pah = Ah + (long long)blockIdx.z * sA + m0 * K;
    const __half* pbh = Bh + (long long)blockIdx.z * sB + n0 * K;

    float acc[2][8][4];
    #pragma unroll
    for (int i = 0; i < 2; i++)
        #pragma unroll
        for (int j = 0; j < 8; j++)
            #pragma unroll
            for (int q = 0; q < 4; q++) acc[i][j][q] = 0.f;

    const int nch = K >> 6;
    cp_tile(sb, pah, K, tid);
    cp_tile(sb + A_TILE, pbh, K, tid);
    CP_COMMIT();

    for (int ch = 0; ch < nch; ch++) {
        CP_WAIT0();
        __syncthreads();
        if (ch + 1 < nch) {
            const size_t k0 = (size_t)(ch + 1) << 6;
            const uint32_t nb = sb + ((ch + 1) & 1) * STG;
            cp_tile(nb, pah + k0, K, tid);
            cp_tile(nb + A_TILE, pbh + k0, K, tid);
            CP_COMMIT();
        }
        const uint32_t cbAH = sb + (ch & 1) * STG;
        const uint32_t cbBH = cbAH + A_TILE;

        #pragma unroll
        for (int ks = 0; ks < 4; ks++) {
            const uint32_t koff = ks * 32 + (lane >> 4) * 16;
            uint32_t a_hi[2][4];
            #pragma unroll
            for (int im = 0; im < 2; im++) {
                uint32_t off = swz((warp_m * 32 + im * 16 + (lane & 15)) * 128 + koff);
                ldm_x4(a_hi[im], cbAH + off);
            }
            #pragma unroll
            for (int in2 = 0; in2 < 4; in2++) {
                uint32_t off = swz((warp_n * 64 + in2 * 16 + (lane & 15)) * 128 + koff);
                uint32_t bh[4];
                ldm_x4(bh, cbBH + off);
                #pragma unroll
                for (int im = 0; im < 2; im++) {
                    #pragma unroll
                    for (int s = 0; s < 2; s++)
                        mma_f16(acc[im][in2 * 2 + s], a_hi[im], bh[s], bh[s + 2]);
                }
            }
        }
        __syncthreads();
    }

    // ---------------- epilogue ----------------
    const long long cbase = (long long)blockIdx.z * sC;
    const long long zrs = (long long)blockIdx.z * NPIX;
    #pragma unroll
    for (int im = 0; im < 2; im++) {
        const int r0 = (int)m0 + warp_m * 32 + im * 16 + (lane >> 2);
        const int r1 = r0 + 8;
        float rb0 = 0.f, rb1 = 0.f;
        if (BIAS_MODE == 1) { rb0 = bias[r0]; rb1 = bias[r1]; }
        float esum0 = 0.f, esum1 = 0.f;
        #pragma unroll
        for (int in = 0; in < 8; in++) {
            const int c = (int)n0 + warp_n * 64 + in * 8 + (lane & 3) * 2;
            float v0 = fmaf(alpha, acc[im][in][0], rb0);
            float v1 = fmaf(alpha, acc[im][in][1], rb0);
            float v2 = fmaf(alpha, acc[im][in][2], rb1);
            float v3 = fmaf(alpha, acc[im][in][3], rb1);
            if (BIAS_MODE == 3) {
                float i0 = __fdividef(1.f, g_rowsum[zrs + c]);
                float i1 = __fdividef(1.f, g_rowsum[zrs + c + 1]);
                v0 *= i0; v1 *= i1; v2 *= i0; v3 *= i1;
            }
            if (OUT_MODE == 3) {
                __half h0 = __float2half(__expf(v0));
                __half h1 = __float2half(__expf(v1));
                __half h2 = __float2half(__expf(v2));
                __half h3 = __float2half(__expf(v3));
                esum0 += __half2float(h0) + __half2float(h1);
                esum1 += __half2float(h2) + __half2float(h3);
                *reinterpret_cast<__half2*>(Ch + cbase + (size_t)r0 * ldc + c) = __halves2half2(h0, h1);
                *reinterpret_cast<__half2*>(Ch + cbase + (size_t)r1 * ldc + c) = __halves2half2(h2, h3);
            } else if (OUT_MODE == 2) {
                *reinterpret_cast<__half2*>(Ch + cbase + (size_t)r0 * ldc + c) =
                    __halves2half2(__float2half(v0), __float2half(v1));
                *reinterpret_cast<__half2*>(Ch + cbase + (size_t)r1 * ldc + c) =
                    __halves2half2(__float2half(v2), __float2half(v3));
            } else {
                *reinterpret_cast<float2*>(Cf + cbase + (size_t)r0 * ldc + c) = make_float2(v0, v1);
                *reinterpret_cast<float2*>(Cf + cbase + (size_t)r1 * ldc + c) = make_float2(v2, v3);
            }
        }
        if (OUT_MODE == 3) {
            esum0 += __shfl_xor_sync(0xffffffffu, esum0, 1);
            esum0 += __shfl_xor_sync(0xffffffffu, esum0, 2);
            esum1 += __shfl_xor_sync(0xffffffffu, esum1, 1);
            esum1 += __shfl_xor_sync(0xffffffffu, esum1, 2);
            if ((lane & 3) == 0) {
                atomicAdd(&g_rowsum[zrs + r0], esum0);
                atomicAdd(&g_rowsum[zrs + r1], esum1);
            }
        }
    }
}

// ================= merged Q/K/V projection GEMM =================
// grid (64, 1, 12): z>>2 = role (0 Q, 1 K, 2 V), z&3 = batch.
// All: K=NC, 1-term, fp16 out. Q/K: M=4096,N=256 col-bias. V: M=256,N=4096 row-bias.
__global__ __launch_bounds__(256, 2)
void proj_gemm(const __half* __restrict__ xs, const __half* __restrict__ xo,
               const __half* __restrict__ qw, const __half* __restrict__ kvw,
               const float* __restrict__ q_b, const float* __restrict__ kv_b,
               __half* __restrict__ qt, __half* __restrict__ kt, __half* __restrict__ v)
{
    constexpr uint32_t STG = 2 * A_TILE;
    extern __shared__ __align__(1024) char dsm[];
    const uint32_t sb = smem_u32(dsm);
    const int tid = threadIdx.x, wid = tid >> 5, lane = tid & 31;
    const int warp_m = wid & 3, warp_n = wid >> 2;
    const int role = blockIdx.z >> 2, b = blockIdx.z & 3;
    const int bx = blockIdx.x;
    const long long sX = (long long)NPIX * NC;

    const __half *Ah, *Bh;
    const float* bias;
    __half* Ch;
    int ldc;
    bool colBias;
    size_t m0, n0;
    if (role == 0) {
        Ah = xs + b * sX; Bh = qw; bias = q_b; Ch = qt + b * sX;
        ldc = NC; colBias = true;
        m0 = (size_t)(bx >> 1) << 7; n0 = (size_t)(bx & 1) << 7;
    } else if (role == 1) {
        Ah = xo + b * sX; Bh = kvw; bias = kv_b; Ch = kt + b * sX;
        ldc = NC; colBias = true;
        m0 = (size_t)(bx >> 1) << 7; n0 = (size_t)(bx & 1) << 7;
    } else {
        Ah = kvw + NC * NC; Bh = xo + b * sX; bias = kv_b + NC; Ch = v + b * sX;
        ldc = NPIX; colBias = false;
        m0 = (size_t)(bx & 1) << 7; n0 = (size_t)(bx >> 1) << 7;
    }
    const __half* pah = Ah + m0 * NC;
    const __half* pbh = Bh + n0 * NC;

    float acc[2][8][4];
    #pragma unroll
    for (int i = 0; i < 2; i++)
        #pragma unroll
        for (int j = 0; j < 8; j++)
            #pragma unroll
            for (int q = 0; q < 4; q++) acc[i][j][q] = 0.f;

    cp_tile(sb, pah, NC, tid);
    cp_tile(sb + A_TILE, pbh, NC, tid);
    CP_COMMIT();

    const int nch = NC >> 6;   // 4
    for (int ch = 0; ch < nch; ch++) {
        CP_WAIT0();
        __syncthreads();
        if (ch + 1 < nch) {
            const size_t k0 = (size_t)(ch + 1) << 6;
            const uint32_t nb = sb + ((ch + 1) & 1) * STG;
            cp_tile(nb, pah + k0, NC, tid);
            cp_tile(nb + A_TILE, pbh + k0, NC, tid);
            CP_COMMIT();
        }
        const uint32_t cbAH = sb + (ch & 1) * STG;
        const uint32_t cbBH = cbAH + A_TILE;

        #pragma unroll
        for (int ks = 0; ks < 4; ks++) {
            const uint32_t koff = ks * 32 + (lane >> 4) * 16;
            uint32_t a_hi[2][4];
            #pragma unroll
            for (int im = 0; im < 2; im++) {
                uint32_t off = swz((warp_m * 32 + im * 16 + (lane & 15)) * 128 + koff);
                ldm_x4(a_hi[im], cbAH + off);
            }
            #pragma unroll
            for (int in2 = 0; in2 < 4; in2++) {
                uint32_t off = swz((warp_n * 64 + in2 * 16 + (lane & 15)) * 128 + koff);
                uint32_t bh[4];
                ldm_x4(bh, cbBH + off);
                #pragma unroll
                for (int im = 0; im < 2; im++) {
                    #pragma unroll
                    for (int s = 0; s < 2; s++)
                        mma_f16(acc[im][in2 * 2 + s], a_hi[im], bh[s], bh[s + 2]);
                }
            }
        }
        __syncthreads();
    }

    // epilogue: fp16 out, runtime row/col bias
    #pragma unroll
    for (int im = 0; im < 2; im++) {
        const int r0 = (int)m0 + warp_m * 32 + im * 16 + (lane >> 2);
        const int r1 = r0 + 8;
        float rb0 = 0.f, rb1 = 0.f;
        if (!colBias) { rb0 = bias[r0]; rb1 = bias[r1]; }
        #pragma unroll
        for (int in = 0; in < 8; in++) {
            const int c = (int)n0 + warp_n * 64 + in * 8 + (lane & 3) * 2;
            float cb0, cb1, cb2, cb3;
            if (colBias) { cb0 = cb2 = bias[c]; cb1 = cb3 = bias[c + 1]; }
            else         { cb0 = cb1 = rb0; cb2 = cb3 = rb1; }
            float v0 = acc[im][in][0] + cb0;
            float v1 = acc[im][in][1] + cb1;
            float v2 = acc[im][in][2] + cb2;
            float v3 = acc[im][in][3] + cb3;
            *reinterpret_cast<__half2*>(Ch + (size_t)r0 * ldc + c) =
                __halves2half2(__float2half(v0), __float2half(v1));
            *reinterpret_cast<__half2*>(Ch + (size_t)r1 * ldc + c) =
                __halves2half2(__float2half(v2), __float2half(v3));
        }
    }
}

// ================= transpose + fp16 convert (hi only), optional channel-pool =================
template<typename T>
__device__ __forceinline__ void tconv_body(const T* src, __half* dh, int R, int C,
                                           float* pool_or_null) {
    __shared__ float t[64][33];
    __shared__ float ps[64];
    const int c0 = blockIdx.x * 32, r0 = blockIdx.y * 64;
    const int tx = threadIdx.x, ty = threadIdx.y;
    const int tid = ty * 32 + tx;
    if (pool_or_null && tid < 64) ps[tid] = 0.f;
    #pragma unroll
    for (int i = 0; i < 8; i++)
        t[ty + 8 * i][tx] = (float)src[(size_t)(r0 + ty + 8 * i) * C + c0 + tx];
    __syncthreads();
    float s0 = 0.f, s1 = 0.f;
    #pragma unroll
    for (int i = 0; i < 4; i++) {
        const int pixl = ty + 8 * i;
        float v0 = t[2 * tx][pixl], v1 = t[2 * tx + 1][pixl];
        size_t o = (size_t)(c0 + pixl) * R + r0 + 2 * tx;
        *reinterpret_cast<__half2*>(dh + o) = __floats2half2_rn(v0, v1);
        s0 += v0; s1 += v1;
    }
    if (pool_or_null) {
        __syncthreads();
        atomicAdd(&ps[2 * tx], s0);
        atomicAdd(&ps[2 * tx + 1], s1);
        __syncthreads();
        if (tid < 64) atomicAdd(&pool_or_null[r0 + tid], ps[tid]);
    }
}

__global__ void tconv_pair(const float* __restrict__ sA, __half* __restrict__ dA,
                           const float* __restrict__ sB, __half* __restrict__ dB,
                           int R, int C)
{
    const int sel = blockIdx.z & 1, b = blockIdx.z >> 1;
    const float* src = (sel ? sB : sA) + (size_t)b * R * C;
    __half* dh = (sel ? dB : dA) + (size_t)b * R * C;
    tconv_body<float>(src, dh, R, C, sel ? nullptr : (g_pool + b * NC));
}

__global__ void tconv1h(const __half* __restrict__ s, __half* __restrict__ d, int R, int C)
{
    tconv_body<__half>(s + (size_t)blockIdx.z * R * C, d + (size_t)blockIdx.z * R * C,
                       R, C, nullptr);
}

// ================= weight convert + scratch zeroing =================
__global__ void wsplit(const float* __restrict__ qw, const float* __restrict__ kvw,
                       const float* __restrict__ ow)
{
    int i = blockIdx.x * 256 + threadIdx.x;   // 0 .. 131071
    if (i < NB * NPIX) g_rowsum[i] = 0.f;
    if (i < NB * NC)   g_pool[i]   = 0.f;
    if (i < NC * NC) {
        g_qw_hi[i] = __float2half(qw[i]);
        g_ow_hi[i] = __float2half(ow[i]);
    }
    if (i < 2 * NC * NC) g_kvw_hi[i] = __float2half(kvw[i]);
}

// ================= gate MLP (tiny; consumes pooled sums) =================
__global__ __launch_bounds__(64)
void gate_mlp(const float* __restrict__ g1w, const float* __restrict__ g1b,
              const float* __restrict__ g2w, const float* __restrict__ g2b)
{
    const int b = blockIdx.x, tid = threadIdx.x;
    __shared__ float p[NC];
    for (int c = tid; c < NC; c += 64) p[c] = g_pool[b * NC + c] * (1.0f / NPIX);
    __syncthreads();
    __shared__ float hbuf[64];
    {
        float s = g1b[tid];
        #pragma unroll 4
        for (int c = 0; c < NC; c++) s = fmaf(g1w[tid * NC + c], p[c], s);
        hbuf[tid] = fmaxf(s, 0.f);
    }
    __syncthreads();
    if (tid == 0) {
        float s = g2b[0];
        #pragma unroll
        for (int o = 0; o < 64; o++) s = fmaf(g2w[o], hbuf[o], s);
        g_gate[b] = 1.f / (1.f + __expf(-s));
    }
}

// ================= dwconv3x3 + BN + SiLU + gate*O^T -> fused fp16 [c][n] =================
__global__ __launch_bounds__(256)
void fuse_kernel(const float* __restrict__ xs,
                 const float* __restrict__ dww, const float* __restrict__ dwb,
                 const float* __restrict__ bng, const float* __restrict__ bnb,
                 const float* __restrict__ bnm, const float* __restrict__ bnv)
{
    const int bc = blockIdx.x;
    const int b = bc >> 8, c = bc & 255;
    const int tid = threadIdx.x;
    __shared__ float t[66 * 66];
    const float* x = xs + (size_t)bc * NPIX;
    for (int i = tid; i < 66 * 66; i += 256) {
        int h = i / 66 - 1, w = i % 66 - 1;
        t[i] = (h >= 0 && h < 64 && w >= 0 && w < 64) ? x[h * 64 + w] : 0.f;
    }
    float wt[9];
    #pragma unroll
    for (int k = 0; k < 9; k++) wt[k] = dww[c * 9 + k];
    float scale = bng[c] * rsqrtf(bnv[c] + 1e-5f);
    float shift = fmaf(dwb[c] - bnm[c], scale, bnb[c]);
    float gate = g_gate[b];
    __half2* fptr2 = reinterpret_cast<__half2*>(g_fusedh + (size_t)bc * NPIX);
    const __half2* optr2 = reinterpret_cast<const __half2*>(g_oh + (size_t)bc * NPIX);
    __syncthreads();
    for (int i = tid; i < NPIX / 2; i += 256) {
        int i2 = 2 * i;
        int h = i2 >> 6, w = i2 & 63;
        const float* tp = &t[h * 66 + w];
        float conv0 = tp[0]   * wt[0] + tp[1]   * wt[1] + tp[2]   * wt[2]
                    + tp[66]  * wt[3] + tp[67]  * wt[4] + tp[68]  * wt[5]
                    + tp[132] * wt[6] + tp[133] * wt[7] + tp[134] * wt[8];
        float conv1 = tp[1]   * wt[0] + tp[2]   * wt[1] + tp[3]   * wt[2]
                    + tp[67]  * wt[3] + tp[68]  * wt[4] + tp[69]  * wt[5]
                    + tp[133] * wt[6] + tp[134] * wt[7] + tp[135] * wt[8];
        float y0 = fmaf(conv0, scale, shift);
        float y1 = fmaf(conv1, scale, shift);
        float lf0 = y0 / (1.f + __expf(-y0));
        float lf1 = y1 / (1.f + __expf(-y1));
        float2 ov = __half22float2(optr2[i]);
        fptr2[i] = __floats2half2_rn(fmaf(gate, ov.x, lf0), fmaf(gate, ov.y, lf1));
    }
}

// ================= launch =================
extern "C" void kernel_launch(void* const* d_in, const int* in_sizes, int n_in,
                              void* d_out, int out_size)
{
    const float* x_self  = (const float*)d_in[0];
    const float* x_other = (const float*)d_in[1];
    const float* q_w  = (const float*)d_in[2];
    const float* q_b  = (const float*)d_in[3];
    const float* kv_w = (const float*)d_in[4];
    const float* kv_b = (const float*)d_in[5];
    const float* g1_w = (const float*)d_in[6];
    const float* g1_b = (const float*)d_in[7];
    const float* g2_w = (const float*)d_in[8];
    const float* g2_b = (const float*)d_in[9];
    const float* dw_w = (const float*)d_in[10];
    const float* dw_b = (const float*)d_in[11];
    const float* bn_g = (const float*)d_in[12];
    const float* bn_b = (const float*)d_in[13];
    const float* bn_m = (const float*)d_in[14];
    const float* bn_v = (const float*)d_in[15];
    const float* out_w = (const float*)d_in[16];
    const float* out_b = (const float*)d_in[17];
    float* out = (float*)d_out;

    cudaFuncSetAttribute(proj_gemm,       cudaFuncAttributeMaxDynamicSharedMemorySize, SMTOT1);
    cudaFuncSetAttribute(mma_gemm<0, 3>,  cudaFuncAttributeMaxDynamicSharedMemorySize, SMTOT1);
    cudaFuncSetAttribute(mma_gemm<3, 2>,  cudaFuncAttributeMaxDynamicSharedMemorySize, SMTOT1);
    cudaFuncSetAttribute(mma_gemm<1, 0>,  cudaFuncAttributeMaxDynamicSharedMemorySize, SMTOT1);

    #define SYM(p, s) cudaGetSymbolAddress((void**)&p, s)
    __half *xsh, *xoh, *qth, *kth, *vh, *ph, *oph, *fph, *fth, *qwh, *kvwh, *owh;
    SYM(xsh, g_xs_hi); SYM(xoh, g_xo_hi);
    SYM(qth, g_qt_hi); SYM(kth, g_kt_hi); SYM(vh, g_v_hi);   SYM(ph, g_p);
    SYM(oph, g_oh);    SYM(fph, g_fusedh); SYM(fth, g_ft_hi);
    SYM(qwh, g_qw_hi); SYM(kvwh, g_kvw_hi); SYM(owh, g_ow_hi);
    #undef SYM

    const long long sX = (long long)NPIX * NC;
    const long long sS = (long long)NPIX * NPIX;

    wsplit<<<2 * NC * NC / 256, 256>>>(q_w, kv_w, out_w);   // also zeroes pool/rowsum
    tconv_pair<<<dim3(NPIX / 32, NC / 64, 2 * NB), dim3(32, 8)>>>(
        x_self, xsh, x_other, xoh, NC, NPIX);               // also pools x_self
    gate_mlp<<<NB, 64>>>(g1_w, g1_b, g2_w, g2_b);

    // Q/K/V projections in one launch (768 CTAs)
    proj_gemm<<<dim3(64, 1, 12), 256, SMTOT1>>>(
        xsh, xoh, qwh, kvwh, q_b, kv_b, qth, kth, vh);

    // P[n][m] = exp((1/16) Qt·Kt^T) fp16 + row sums
    mma_gemm<0, 3><<<dim3(32, 32, NB), 256, SMTOT1>>>(
        qth, kth, nullptr, 0.0625f, nullptr, ph, NC, NPIX, sX, sX, sS);

    // O^T[c][n] = (sum_m V[c][m] P[n][m]) / rowsum[n]   (fp16 out)
    mma_gemm<3, 2><<<dim3(32, 2, NB), 256, SMTOT1>>>(
        vh, ph, nullptr, 1.f, nullptr, oph, NPIX, NPIX, sX, sS, sX);

    fuse_kernel<<<NB * NC, 256>>>(x_self, dw_w, dw_b, bn_g, bn_b, bn_m, bn_v);
    tconv1h<<<dim3(NPIX / 32, NC / 64, NB), dim3(32, 8)>>>(fph, fth, NC, NPIX);

    // out[o][n] = sum_c ow[o][c] ft[n][c] + out_b[o]   (fp32, row bias)
    mma_gemm<1, 0><<<dim3(32, 2, NB), 256, SMTOT1>>>(
        owh, fth, out_b, 1.f, out, nullptr, NC, NPIX, 0, sX, sX);
}